// round 1
// baseline (speedup 1.0000x reference)
#include <cuda_runtime.h>
#include <math.h>

// Problem constants
#define Bq   8
#define Nq   8192
#define Cq   256
#define Hq   8
#define Dq   32
#define Sq   32
#define HIDq 1024
#define Mq   (Bq * Nq)        // 65536 rows
#define BHq  (Bq * Hq)        // 64
#define KV_CHUNKS 4           // token chunks for deterministic kv reduction

// ---------------- scratch (static device arrays; no allocation) -------------
__device__ float g_xln [Mq * Cq];
__device__ float g_xmid[Mq * Cq];
__device__ float g_q   [Mq * Cq];   // [(b*H+h)*N + n]*32 + s
__device__ float g_ek  [Mq * Cq];   // exp(k logits), same layout
__device__ float g_v   [Mq * Cq];   // v, same layout (d instead of s)
__device__ float g_ekvp[KV_CHUNKS * BHq * Sq * Dq];  // partial sums
__device__ float g_csp [KV_CHUNKS * BHq * Sq];       // partial col sums
__device__ float g_kv  [BHq * Sq * Dq];              // normalized kv
__device__ float g_qkv [Mq * Cq];
__device__ float g_h   [Mq * Cq];
__device__ float g_y   [Mq * Cq];
__device__ float g_hid [Mq * HIDq];

// ---------------- LayerNorm: one warp per row (C=256) -----------------------
__global__ void ln_kernel(const float* __restrict__ x,
                          const float* __restrict__ w,
                          const float* __restrict__ bb,
                          float* __restrict__ out) {
    int row  = blockIdx.x * 8 + threadIdx.y;
    int lane = threadIdx.x;
    const float* xr = x + (size_t)row * Cq;
    float v[8];
    float s = 0.f, s2 = 0.f;
#pragma unroll
    for (int i = 0; i < 8; i++) {
        float t = xr[lane + i * 32];
        v[i] = t; s += t; s2 += t * t;
    }
#pragma unroll
    for (int o = 16; o > 0; o >>= 1) {
        s  += __shfl_xor_sync(0xffffffffu, s,  o);
        s2 += __shfl_xor_sync(0xffffffffu, s2, o);
    }
    float mu  = s * (1.f / Cq);
    float var = s2 * (1.f / Cq) - mu * mu;
    float rs  = rsqrtf(var + 1e-5f);
    float* orow = out + (size_t)row * Cq;
#pragma unroll
    for (int i = 0; i < 8; i++) {
        int c = lane + i * 32;
        orow[c] = (v[i] - mu) * rs * w[c] + bb[c];
    }
}

// ---------------- SGEMM: C = A[M,K] @ W[Ncols,K]^T + bias (+epilogue) -------
// EPI: 0 = bias only, 1 = bias + residual, 2 = bias + exact GELU
__device__ __forceinline__ float gelu_exact(float v) {
    return 0.5f * v * (1.f + erff(v * 0.70710678118654752f));
}

template <int EPI>
__global__ __launch_bounds__(256, 2) void sgemm_kernel(
    const float* __restrict__ A, const float* __restrict__ W,
    const float* __restrict__ bias, const float* __restrict__ res,
    float* __restrict__ Cout, int Ncols, int K) {
    const int BM = 128, BN = 128, BK = 16;
    __shared__ __align__(16) float As[BK][BM + 4];
    __shared__ __align__(16) float Bs[BK][BN + 4];

    int tid = threadIdx.x;
    int tx = tid & 15, ty = tid >> 4;
    int lr = tid >> 2;           // 0..63
    int lc = (tid & 3) * 4;      // 0,4,8,12

    const float* Ab = A + (size_t)blockIdx.y * BM * K;
    const float* Wb = W + (size_t)blockIdx.x * BN * K;

    float acc[8][8];
#pragma unroll
    for (int i = 0; i < 8; i++)
#pragma unroll
        for (int j = 0; j < 8; j++) acc[i][j] = 0.f;

    // preload tile 0
    float4 a0 = *(const float4*)&Ab[(size_t)lr * K + lc];
    float4 a1 = *(const float4*)&Ab[(size_t)(lr + 64) * K + lc];
    float4 b0 = *(const float4*)&Wb[(size_t)lr * K + lc];
    float4 b1 = *(const float4*)&Wb[(size_t)(lr + 64) * K + lc];

    int ntiles = K / BK;
    for (int kt = 0; kt < ntiles; kt++) {
        __syncthreads();
        As[lc + 0][lr]      = a0.x; As[lc + 1][lr]      = a0.y;
        As[lc + 2][lr]      = a0.z; As[lc + 3][lr]      = a0.w;
        As[lc + 0][lr + 64] = a1.x; As[lc + 1][lr + 64] = a1.y;
        As[lc + 2][lr + 64] = a1.z; As[lc + 3][lr + 64] = a1.w;
        Bs[lc + 0][lr]      = b0.x; Bs[lc + 1][lr]      = b0.y;
        Bs[lc + 2][lr]      = b0.z; Bs[lc + 3][lr]      = b0.w;
        Bs[lc + 0][lr + 64] = b1.x; Bs[lc + 1][lr + 64] = b1.y;
        Bs[lc + 2][lr + 64] = b1.z; Bs[lc + 3][lr + 64] = b1.w;
        __syncthreads();

        if (kt + 1 < ntiles) {
            int ko = (kt + 1) * BK + lc;
            a0 = *(const float4*)&Ab[(size_t)lr * K + ko];
            a1 = *(const float4*)&Ab[(size_t)(lr + 64) * K + ko];
            b0 = *(const float4*)&Wb[(size_t)lr * K + ko];
            b1 = *(const float4*)&Wb[(size_t)(lr + 64) * K + ko];
        }

#pragma unroll
        for (int k = 0; k < BK; k++) {
            float4 av0 = *(const float4*)&As[k][ty * 8];
            float4 av1 = *(const float4*)&As[k][ty * 8 + 4];
            float4 bv0 = *(const float4*)&Bs[k][tx * 8];
            float4 bv1 = *(const float4*)&Bs[k][tx * 8 + 4];
            float ar[8] = {av0.x, av0.y, av0.z, av0.w, av1.x, av1.y, av1.z, av1.w};
            float br[8] = {bv0.x, bv0.y, bv0.z, bv0.w, bv1.x, bv1.y, bv1.z, bv1.w};
#pragma unroll
            for (int i = 0; i < 8; i++)
#pragma unroll
                for (int j = 0; j < 8; j++) acc[i][j] += ar[i] * br[j];
        }
    }

    int m0 = blockIdx.y * BM + ty * 8;
    int n0 = blockIdx.x * BN + tx * 8;
#pragma unroll
    for (int i = 0; i < 8; i++) {
        size_t off = (size_t)(m0 + i) * Ncols + n0;
#pragma unroll
        for (int j = 0; j < 8; j++) {
            float val = acc[i][j] + bias[n0 + j];
            if (EPI == 1) val += res[off + j];
            if (EPI == 2) val = gelu_exact(val);
            Cout[off + j] = val;
        }
    }
}

// ------------- per-head q/k/v projection + softmaxes (fused) ----------------
// block = 128 tokens of one (b,h); thread = one token
__global__ __launch_bounds__(128) void head_proj_kernel(
    const float* __restrict__ xmid,
    const float* __restrict__ Wq, const float* __restrict__ Wk,
    const float* __restrict__ Wv,
    float* __restrict__ qo, float* __restrict__ eko, float* __restrict__ vo) {
    __shared__ float xs[128][33];
    __shared__ float wq[Sq * Dq], wk[Sq * Dq], wv[Dq * Dq];
    int tid = threadIdx.x;
    int h = blockIdx.y, b = blockIdx.z;
    int n0 = blockIdx.x * 128;

#pragma unroll
    for (int i = 0; i < 8; i++) {
        int idx = tid + i * 128;
        wq[idx] = Wq[idx]; wk[idx] = Wk[idx]; wv[idx] = Wv[idx];
    }
    size_t base = ((size_t)(b * Nq + n0)) * Cq + h * Dq;
#pragma unroll
    for (int i = 0; i < 32; i++) {
        int idx = tid + i * 128;
        int t = idx >> 5, d = idx & 31;
        xs[t][d] = xmid[base + (size_t)t * Cq + d];
    }
    __syncthreads();

    float x[32];
#pragma unroll
    for (int d = 0; d < 32; d++) x[d] = xs[tid][d];
    __syncthreads();  // xs free for staging

    size_t obase = ((size_t)((b * Hq + h) * (size_t)Nq + n0)) * 32;

    // q = softmax over s
    {
        float e[32]; float ssum = 0.f;
#pragma unroll
        for (int s = 0; s < 32; s++) {
            float a = 0.f;
#pragma unroll
            for (int d = 0; d < 32; d++) a += x[d] * wq[s * 32 + d];
            e[s] = expf(a); ssum += e[s];
        }
        float r = 1.f / ssum;
#pragma unroll
        for (int s = 0; s < 32; s++) xs[tid][s] = e[s] * r;
        __syncthreads();
#pragma unroll
        for (int i = 0; i < 32; i++) {
            int idx = tid + i * 128;
            qo[obase + idx] = xs[idx >> 5][idx & 31];
        }
        __syncthreads();
    }
    // ek = exp(k logits)  (token-axis normalization happens in kv_finalize)
    {
#pragma unroll
        for (int s = 0; s < 32; s++) {
            float a = 0.f;
#pragma unroll
            for (int d = 0; d < 32; d++) a += x[d] * wk[s * 32 + d];
            xs[tid][s] = expf(a);
        }
        __syncthreads();
#pragma unroll
        for (int i = 0; i < 32; i++) {
            int idx = tid + i * 128;
            eko[obase + idx] = xs[idx >> 5][idx & 31];
        }
        __syncthreads();
    }
    // v = x @ Wv^T
    {
#pragma unroll
        for (int dp = 0; dp < 32; dp++) {
            float a = 0.f;
#pragma unroll
            for (int d = 0; d < 32; d++) a += x[d] * wv[dp * 32 + d];
            xs[tid][dp] = a;
        }
        __syncthreads();
#pragma unroll
        for (int i = 0; i < 32; i++) {
            int idx = tid + i * 128;
            vo[obase + idx] = xs[idx >> 5][idx & 31];
        }
    }
}

// ---------- kv partial reduction: ekv[s,d] = sum_n ek[n,s]*v[n,d] ------------
__global__ __launch_bounds__(256) void ekv_reduce_kernel(
    const float* __restrict__ ek, const float* __restrict__ v) {
    int tid = threadIdx.x;
    int s = tid & 31;
    int d0 = (tid >> 5) * 4;
    int h = blockIdx.y, b = blockIdx.z;
    int bh = b * Hq + h;
    int ch = blockIdx.x;                 // chunk index
    int n0 = ch * (Nq / KV_CHUNKS);      // 2048 tokens per chunk

    __shared__ float es[64][33], vs[64][33];
    float a0 = 0.f, a1 = 0.f, a2 = 0.f, a3 = 0.f, cs = 0.f;
    size_t base = ((size_t)bh * Nq + n0) * 32;

    for (int t0 = 0; t0 < Nq / KV_CHUNKS; t0 += 64) {
#pragma unroll
        for (int i = 0; i < 8; i++) {
            int idx = tid + i * 256;
            int t = idx >> 5, dd = idx & 31;
            es[t][dd] = ek[base + (size_t)(t0 + t) * 32 + dd];
            vs[t][dd] = v [base + (size_t)(t0 + t) * 32 + dd];
        }
        __syncthreads();
#pragma unroll 4
        for (int t = 0; t < 64; t++) {
            float e = es[t][s];
            cs += e;
            a0 += e * vs[t][d0 + 0];
            a1 += e * vs[t][d0 + 1];
            a2 += e * vs[t][d0 + 2];
            a3 += e * vs[t][d0 + 3];
        }
        __syncthreads();
    }
    float* ep = &g_ekvp[((size_t)ch * BHq + bh) * (Sq * Dq) + s * 32 + d0];
    ep[0] = a0; ep[1] = a1; ep[2] = a2; ep[3] = a3;
    if (d0 == 0) g_csp[((size_t)ch * BHq + bh) * Sq + s] = cs;
}

// ---------- kv finalize: sum chunks deterministically, normalize ------------
__global__ void kv_finalize_kernel() {
    int bh = blockIdx.x;
    int tid = threadIdx.x;
    __shared__ float rcs[32];
    if (tid < 32) {
        float c = 0.f;
#pragma unroll
        for (int ch = 0; ch < KV_CHUNKS; ch++)
            c += g_csp[((size_t)ch * BHq + bh) * Sq + tid];
        rcs[tid] = 1.f / c;
    }
    __syncthreads();
    for (int idx = tid; idx < Sq * Dq; idx += blockDim.x) {
        float vsum = 0.f;
#pragma unroll
        for (int ch = 0; ch < KV_CHUNKS; ch++)
            vsum += g_ekvp[((size_t)ch * BHq + bh) * (Sq * Dq) + idx];
        g_kv[(size_t)bh * (Sq * Dq) + idx] = vsum * rcs[idx >> 5];
    }
}

// ---------- qkv = q @ kv, concat heads back into [B,N,C] ---------------------
__global__ __launch_bounds__(128) void qkv_apply_kernel(
    const float* __restrict__ q, float* __restrict__ qkvo) {
    __shared__ float qs[128][33];
    __shared__ float kvs[32][33];
    int tid = threadIdx.x;
    int h = blockIdx.y, b = blockIdx.z, bh = b * Hq + h;
    int n0 = blockIdx.x * 128;

#pragma unroll
    for (int i = 0; i < 8; i++) {
        int idx = tid + i * 128;
        kvs[idx >> 5][idx & 31] = g_kv[(size_t)bh * (Sq * Dq) + idx];
    }
    size_t qbase = ((size_t)bh * Nq + n0) * 32;
#pragma unroll
    for (int i = 0; i < 32; i++) {
        int idx = tid + i * 128;
        qs[idx >> 5][idx & 31] = q[qbase + idx];
    }
    __syncthreads();

    float qv[32];
#pragma unroll
    for (int s = 0; s < 32; s++) qv[s] = qs[tid][s];
    float o[32];
#pragma unroll
    for (int d = 0; d < 32; d++) o[d] = 0.f;
#pragma unroll
    for (int s = 0; s < 32; s++) {
        float qq = qv[s];
#pragma unroll
        for (int d = 0; d < 32; d++) o[d] += qq * kvs[s][d];
    }
    __syncthreads();
#pragma unroll
    for (int d = 0; d < 32; d++) qs[tid][d] = o[d];
    __syncthreads();

    size_t obase = ((size_t)(b * Nq + n0)) * Cq + h * Dq;
#pragma unroll
    for (int i = 0; i < 32; i++) {
        int idx = tid + i * 128;
        int t = idx >> 5, d = idx & 31;
        qkvo[obase + (size_t)t * Cq + d] = qs[t][d];
    }
}

// ---------------------------- launcher ---------------------------------------
extern "C" void kernel_launch(void* const* d_in, const int* in_sizes, int n_in,
                              void* d_out, int out_size) {
    const float* fx   = (const float*)d_in[0];
    const float* ln1w = (const float*)d_in[1];
    const float* ln1b = (const float*)d_in[2];
    const float* Wx   = (const float*)d_in[3];
    const float* bx   = (const float*)d_in[4];
    const float* Wqp  = (const float*)d_in[5];
    const float* Wkp  = (const float*)d_in[6];
    const float* Wvp  = (const float*)d_in[7];
    const float* Wo   = (const float*)d_in[8];
    const float* bo   = (const float*)d_in[9];
    const float* ln2w = (const float*)d_in[10];
    const float* ln2b = (const float*)d_in[11];
    const float* W1   = (const float*)d_in[12];
    const float* b1   = (const float*)d_in[13];
    const float* W2   = (const float*)d_in[14];
    const float* b2   = (const float*)d_in[15];
    float* out = (float*)d_out;

    float *p_xln, *p_xmid, *p_q, *p_ek, *p_v, *p_qkv, *p_h, *p_y, *p_hid;
    cudaGetSymbolAddress((void**)&p_xln,  g_xln);
    cudaGetSymbolAddress((void**)&p_xmid, g_xmid);
    cudaGetSymbolAddress((void**)&p_q,    g_q);
    cudaGetSymbolAddress((void**)&p_ek,   g_ek);
    cudaGetSymbolAddress((void**)&p_v,    g_v);
    cudaGetSymbolAddress((void**)&p_qkv,  g_qkv);
    cudaGetSymbolAddress((void**)&p_h,    g_h);
    cudaGetSymbolAddress((void**)&p_y,    g_y);
    cudaGetSymbolAddress((void**)&p_hid,  g_hid);

    dim3 lnBlk(32, 8);
    // 1) LN1
    ln_kernel<<<Mq / 8, lnBlk>>>(fx, ln1w, ln1b, p_xln);
    // 2) x_mid = xln @ Wx^T + bx
    sgemm_kernel<0><<<dim3(Cq / 128, Mq / 128), 256>>>(p_xln, Wx, bx, nullptr, p_xmid, Cq, Cq);
    // 3) per-head q/k/v + softmaxes
    head_proj_kernel<<<dim3(Nq / 128, Hq, Bq), 128>>>(p_xmid, Wqp, Wkp, Wvp, p_q, p_ek, p_v);
    // 4) kv partial reduction (deterministic chunks)
    ekv_reduce_kernel<<<dim3(KV_CHUNKS, Hq, Bq), 256>>>(p_ek, p_v);
    // 5) finalize kv (sum chunks, normalize by column sums)
    kv_finalize_kernel<<<BHq, 256>>>();
    // 6) qkv = q @ kv  (concat heads)
    qkv_apply_kernel<<<dim3(Nq / 128, Hq, Bq), 128>>>(p_q, p_qkv);
    // 7) h = qkv @ Wo^T + bo + fx
    sgemm_kernel<1><<<dim3(Cq / 128, Mq / 128), 256>>>(p_qkv, Wo, bo, fx, p_h, Cq, Cq);
    // 8) LN2
    ln_kernel<<<Mq / 8, lnBlk>>>(p_h, ln2w, ln2b, p_y);
    // 9) hid = gelu(y @ W1^T + b1)
    sgemm_kernel<2><<<dim3(HIDq / 128, Mq / 128), 256>>>(p_y, W1, b1, nullptr, p_hid, HIDq, Cq);
    // 10) out = hid @ W2^T + b2 + h
    sgemm_kernel<1><<<dim3(Cq / 128, Mq / 128), 256>>>(p_hid, W2, b2, p_h, out, Cq, HIDq);
}

// round 3
// speedup vs baseline: 2.8986x; 2.8986x over previous
#include <cuda_runtime.h>
#include <math.h>
#include <stdint.h>

// Problem constants
#define Bq   8
#define Nq   8192
#define Cq   256
#define Hq   8
#define Dq   32
#define Sq   32
#define HIDq 1024
#define Mq   (Bq * Nq)        // 65536 rows
#define BHq  (Bq * Hq)        // 64
#define KV_CHUNKS 16

// GEMM tiling
#define BM 128
#define BN 128
#define BKq 32
#define STAGE_F ((BM + BN) * BKq)          // floats per stage
#define GEMM_SMEM (2 * STAGE_F * 4)        // bytes (2 stages)

// ---------------- scratch (static device arrays; no allocation) -------------
__device__ float g_xln [Mq * Cq];
__device__ float g_xmid[Mq * Cq];
__device__ float g_q   [Mq * Cq];
__device__ float g_ek  [Mq * Cq];
__device__ float g_v   [Mq * Cq];
__device__ float g_ekvp[KV_CHUNKS * BHq * Sq * Dq];
__device__ float g_csp [KV_CHUNKS * BHq * Sq];
__device__ float g_kv  [BHq * Sq * Dq];
__device__ float g_qkv [Mq * Cq];
__device__ float g_h   [Mq * Cq];
__device__ float g_y   [Mq * Cq];
__device__ float g_hid [Mq * HIDq];

// ------------------------------ PTX helpers ---------------------------------
__device__ __forceinline__ uint32_t smem_u32(const void* p) {
    uint32_t a;
    asm("{ .reg .u64 t; cvta.to.shared.u64 t, %1; cvt.u32.u64 %0, t; }"
        : "=r"(a) : "l"(p));
    return a;
}
__device__ __forceinline__ uint32_t f2tf32(float x) {
    uint32_t r;
    asm("cvt.rna.tf32.f32 %0, %1;" : "=r"(r) : "f"(x));
    return r;
}
__device__ __forceinline__ void cp_async16(uint32_t dst, const void* src) {
    asm volatile("cp.async.ca.shared.global [%0], [%1], 16;"
                 :: "r"(dst), "l"(src));
}
__device__ __forceinline__ void cp_commit() {
    asm volatile("cp.async.commit_group;");
}
template <int N>
__device__ __forceinline__ void cp_wait() {
    asm volatile("cp.async.wait_group %0;" :: "n"(N));
}
__device__ __forceinline__ void mma_tf32(float* c, const uint32_t* a, const uint32_t* b) {
    asm volatile(
        "mma.sync.aligned.m16n8k8.row.col.f32.tf32.tf32.f32 "
        "{%0,%1,%2,%3}, {%4,%5,%6,%7}, {%8,%9}, {%0,%1,%2,%3};"
        : "+f"(c[0]), "+f"(c[1]), "+f"(c[2]), "+f"(c[3])
        : "r"(a[0]), "r"(a[1]), "r"(a[2]), "r"(a[3]), "r"(b[0]), "r"(b[1]));
}

// ---------------- LayerNorm: one warp per row (C=256) -----------------------
__global__ void ln_kernel(const float* __restrict__ x,
                          const float* __restrict__ w,
                          const float* __restrict__ bb,
                          float* __restrict__ out) {
    int row  = blockIdx.x * 8 + threadIdx.y;
    int lane = threadIdx.x;
    const float* xr = x + (size_t)row * Cq;
    float v[8];
    float s = 0.f, s2 = 0.f;
#pragma unroll
    for (int i = 0; i < 8; i++) {
        float t = xr[lane + i * 32];
        v[i] = t; s += t; s2 += t * t;
    }
#pragma unroll
    for (int o = 16; o > 0; o >>= 1) {
        s  += __shfl_xor_sync(0xffffffffu, s,  o);
        s2 += __shfl_xor_sync(0xffffffffu, s2, o);
    }
    float mu  = s * (1.f / Cq);
    float var = s2 * (1.f / Cq) - mu * mu;
    float rs  = rsqrtf(var + 1e-5f);
    float* orow = out + (size_t)row * Cq;
#pragma unroll
    for (int i = 0; i < 8; i++) {
        int c = lane + i * 32;
        orow[c] = (v[i] - mu) * rs * w[c] + bb[c];
    }
}

// ------------- mma.sync tf32 GEMM: C = A[M,K] @ W[Ncols,K]^T + bias ---------
// EPI: 0 = bias, 1 = bias + residual, 2 = bias + exact GELU
__device__ __forceinline__ float gelu_exact(float v) {
    return 0.5f * v * (1.f + erff(v * 0.70710678118654752f));
}

// swizzled float-column within a 32-float row: groups of 4 floats XORed by row
__device__ __forceinline__ int swcol(int row, int k) {
    return (k & 3) | ((k & 0x1C) ^ ((row & 7) << 2));
}

template <int EPI>
__global__ __launch_bounds__(256) void tgemm_kernel(
    const float* __restrict__ A, const float* __restrict__ W,
    const float* __restrict__ bias, const float* __restrict__ res,
    float* __restrict__ Cout, int Ncols, int K) {
    extern __shared__ float smem[];
    int tid  = threadIdx.x;
    int wid  = tid >> 5, lane = tid & 31;
    int g = lane >> 2, q = lane & 3;
    int warp_m = wid >> 2;        // 0..1 -> 64 rows
    int warp_n = wid & 3;         // 0..3 -> 32 cols

    uint32_t sbase = smem_u32(smem);
    const float* Ab = A + (size_t)blockIdx.y * BM * K;
    const float* Wb = W + (size_t)blockIdx.x * BN * K;

    float acc[4][4][4];
#pragma unroll
    for (int mt = 0; mt < 4; mt++)
#pragma unroll
        for (int nt = 0; nt < 4; nt++)
#pragma unroll
            for (int i = 0; i < 4; i++) acc[mt][nt][i] = 0.f;

    int ntiles = K >> 5;

    // staging assignment: idx in [0,1024) covers one 128x32 tile as float4s
    // thread does 4 float4 for A and 4 for B per tile
    auto load_tile = [&](int stage, int kt) {
        uint32_t aoff = sbase + stage * STAGE_F * 4;
        uint32_t boff = aoff + BM * BKq * 4;
        int k0 = kt << 5;
#pragma unroll
        for (int i = 0; i < 4; i++) {
            int idx = i * 256 + tid;
            int row = idx >> 3;
            int j   = idx & 7;                       // float4 group
            int c4  = ((j << 2) ^ ((row & 7) << 2)); // swizzled float col
            cp_async16(aoff + (row * BKq + c4) * 4, &Ab[(size_t)row * K + k0 + (j << 2)]);
            cp_async16(boff + (row * BKq + c4) * 4, &Wb[(size_t)row * K + k0 + (j << 2)]);
        }
    };

    load_tile(0, 0);
    cp_commit();

    for (int kt = 0; kt < ntiles; kt++) {
        int cur = kt & 1;
        if (kt + 1 < ntiles) {
            load_tile(cur ^ 1, kt + 1);
            cp_commit();
            cp_wait<1>();
        } else {
            cp_wait<0>();
        }
        __syncthreads();

        const float* As = smem + cur * STAGE_F;
        const float* Bs = As + BM * BKq;

#pragma unroll
        for (int ks = 0; ks < 4; ks++) {
            int k_lo = ks * 8;
            uint32_t af[4][4];
#pragma unroll
            for (int mt = 0; mt < 4; mt++) {
                int r0 = warp_m * 64 + mt * 16 + g;
                int r1 = r0 + 8;
                int c_lo = q | ((k_lo)     ^ ((r0 & 7) << 2));
                int c_hi = q | ((k_lo + 4) ^ ((r0 & 7) << 2));
                af[mt][0] = f2tf32(As[r0 * BKq + c_lo]);
                af[mt][1] = f2tf32(As[r1 * BKq + c_lo]);
                af[mt][2] = f2tf32(As[r0 * BKq + c_hi]);
                af[mt][3] = f2tf32(As[r1 * BKq + c_hi]);
            }
            uint32_t bf[4][2];
#pragma unroll
            for (int nt = 0; nt < 4; nt++) {
                int rn = warp_n * 32 + nt * 8 + g;
                int c_lo = q | ((k_lo)     ^ ((rn & 7) << 2));
                int c_hi = q | ((k_lo + 4) ^ ((rn & 7) << 2));
                bf[nt][0] = f2tf32(Bs[rn * BKq + c_lo]);
                bf[nt][1] = f2tf32(Bs[rn * BKq + c_hi]);
            }
#pragma unroll
            for (int mt = 0; mt < 4; mt++)
#pragma unroll
                for (int nt = 0; nt < 4; nt++)
                    mma_tf32(acc[mt][nt], af[mt], bf[nt]);
        }
        __syncthreads();
    }

    // Epilogue: direct register -> global
    int mBase = blockIdx.y * BM + warp_m * 64;
    int nBase = blockIdx.x * BN + warp_n * 32;
#pragma unroll
    for (int nt = 0; nt < 4; nt++) {
        int c0 = nBase + nt * 8 + q * 2;
        float bv0 = bias[c0], bv1 = bias[c0 + 1];
#pragma unroll
        for (int mt = 0; mt < 4; mt++) {
            int r0 = mBase + mt * 16 + g;
#pragma unroll
            for (int half = 0; half < 2; half++) {
                int r = r0 + half * 8;
                size_t off = (size_t)r * Ncols + c0;
                float v0 = acc[mt][nt][half * 2 + 0] + bv0;
                float v1 = acc[mt][nt][half * 2 + 1] + bv1;
                if (EPI == 1) {
                    float2 rr = *(const float2*)&res[off];
                    v0 += rr.x; v1 += rr.y;
                }
                if (EPI == 2) { v0 = gelu_exact(v0); v1 = gelu_exact(v1); }
                *(float2*)&Cout[off] = make_float2(v0, v1);
            }
        }
    }
}

// ------------- per-head q/k/v projection + softmaxes (fused) ----------------
__global__ __launch_bounds__(128) void head_proj_kernel(
    const float* __restrict__ xmid,
    const float* __restrict__ Wq, const float* __restrict__ Wk,
    const float* __restrict__ Wv,
    float* __restrict__ qo, float* __restrict__ eko, float* __restrict__ vo) {
    __shared__ float xs[128][33];
    __shared__ float wq[Sq * Dq], wk[Sq * Dq], wv[Dq * Dq];
    int tid = threadIdx.x;
    int h = blockIdx.y, b = blockIdx.z;
    int n0 = blockIdx.x * 128;

#pragma unroll
    for (int i = 0; i < 8; i++) {
        int idx = tid + i * 128;
        wq[idx] = Wq[idx]; wk[idx] = Wk[idx]; wv[idx] = Wv[idx];
    }
    size_t base = ((size_t)(b * Nq + n0)) * Cq + h * Dq;
#pragma unroll
    for (int i = 0; i < 32; i++) {
        int idx = tid + i * 128;
        int t = idx >> 5, d = idx & 31;
        xs[t][d] = xmid[base + (size_t)t * Cq + d];
    }
    __syncthreads();

    float x[32];
#pragma unroll
    for (int d = 0; d < 32; d++) x[d] = xs[tid][d];
    __syncthreads();

    size_t obase = ((size_t)((b * Hq + h) * (size_t)Nq + n0)) * 32;

    {
        float e[32]; float ssum = 0.f;
#pragma unroll
        for (int s = 0; s < 32; s++) {
            float a = 0.f;
#pragma unroll
            for (int d = 0; d < 32; d++) a += x[d] * wq[s * 32 + d];
            e[s] = expf(a); ssum += e[s];
        }
        float r = 1.f / ssum;
#pragma unroll
        for (int s = 0; s < 32; s++) xs[tid][s] = e[s] * r;
        __syncthreads();
#pragma unroll
        for (int i = 0; i < 32; i++) {
            int idx = tid + i * 128;
            qo[obase + idx] = xs[idx >> 5][idx & 31];
        }
        __syncthreads();
    }
    {
#pragma unroll
        for (int s = 0; s < 32; s++) {
            float a = 0.f;
#pragma unroll
            for (int d = 0; d < 32; d++) a += x[d] * wk[s * 32 + d];
            xs[tid][s] = expf(a);
        }
        __syncthreads();
#pragma unroll
        for (int i = 0; i < 32; i++) {
            int idx = tid + i * 128;
            eko[obase + idx] = xs[idx >> 5][idx & 31];
        }
        __syncthreads();
    }
    {
#pragma unroll
        for (int dp = 0; dp < 32; dp++) {
            float a = 0.f;
#pragma unroll
            for (int d = 0; d < 32; d++) a += x[d] * wv[dp * 32 + d];
            xs[tid][dp] = a;
        }
        __syncthreads();
#pragma unroll
        for (int i = 0; i < 32; i++) {
            int idx = tid + i * 128;
            vo[obase + idx] = xs[idx >> 5][idx & 31];
        }
    }
}

// ---------- kv partial reduction: ekv[s,d] = sum_n ek[n,s]*v[n,d] ------------
__global__ __launch_bounds__(256) void ekv_reduce_kernel(
    const float* __restrict__ ek, const float* __restrict__ v) {
    int tid = threadIdx.x;
    int s = tid & 31;
    int d0 = (tid >> 5) * 4;
    int h = blockIdx.y, b = blockIdx.z;
    int bh = b * Hq + h;
    int ch = blockIdx.x;
    int n0 = ch * (Nq / KV_CHUNKS);

    __shared__ float es[64][33], vs[64][33];
    float a0 = 0.f, a1 = 0.f, a2 = 0.f, a3 = 0.f, cs = 0.f;
    size_t base = ((size_t)bh * Nq + n0) * 32;

    for (int t0 = 0; t0 < Nq / KV_CHUNKS; t0 += 64) {
#pragma unroll
        for (int i = 0; i < 8; i++) {
            int idx = tid + i * 256;
            int t = idx >> 5, dd = idx & 31;
            es[t][dd] = ek[base + (size_t)(t0 + t) * 32 + dd];
            vs[t][dd] = v [base + (size_t)(t0 + t) * 32 + dd];
        }
        __syncthreads();
#pragma unroll 4
        for (int t = 0; t < 64; t++) {
            float e = es[t][s];
            cs += e;
            a0 += e * vs[t][d0 + 0];
            a1 += e * vs[t][d0 + 1];
            a2 += e * vs[t][d0 + 2];
            a3 += e * vs[t][d0 + 3];
        }
        __syncthreads();
    }
    float* ep = &g_ekvp[((size_t)ch * BHq + bh) * (Sq * Dq) + s * 32 + d0];
    ep[0] = a0; ep[1] = a1; ep[2] = a2; ep[3] = a3;
    if (d0 == 0) g_csp[((size_t)ch * BHq + bh) * Sq + s] = cs;
}

// ---------- kv finalize: sum chunks deterministically, normalize ------------
__global__ void kv_finalize_kernel() {
    int bh = blockIdx.x;
    int tid = threadIdx.x;
    __shared__ float rcs[32];
    if (tid < 32) {
        float c = 0.f;
#pragma unroll
        for (int ch = 0; ch < KV_CHUNKS; ch++)
            c += g_csp[((size_t)ch * BHq + bh) * Sq + tid];
        rcs[tid] = 1.f / c;
    }
    __syncthreads();
    for (int idx = tid; idx < Sq * Dq; idx += blockDim.x) {
        float vsum = 0.f;
#pragma unroll
        for (int ch = 0; ch < KV_CHUNKS; ch++)
            vsum += g_ekvp[((size_t)ch * BHq + bh) * (Sq * Dq) + idx];
        g_kv[(size_t)bh * (Sq * Dq) + idx] = vsum * rcs[idx >> 5];
    }
}

// ---------- qkv = q @ kv, concat heads back into [B,N,C] ---------------------
__global__ __launch_bounds__(128) void qkv_apply_kernel(
    const float* __restrict__ q, float* __restrict__ qkvo) {
    __shared__ float qs[128][33];
    __shared__ float kvs[32][33];
    int tid = threadIdx.x;
    int h = blockIdx.y, b = blockIdx.z, bh = b * Hq + h;
    int n0 = blockIdx.x * 128;

#pragma unroll
    for (int i = 0; i < 8; i++) {
        int idx = tid + i * 128;
        kvs[idx >> 5][idx & 31] = g_kv[(size_t)bh * (Sq * Dq) + idx];
    }
    size_t qbase = ((size_t)bh * Nq + n0) * 32;
#pragma unroll
    for (int i = 0; i < 32; i++) {
        int idx = tid + i * 128;
        qs[idx >> 5][idx & 31] = q[qbase + idx];
    }
    __syncthreads();

    float qv[32];
#pragma unroll
    for (int s = 0; s < 32; s++) qv[s] = qs[tid][s];
    float o[32];
#pragma unroll
    for (int d = 0; d < 32; d++) o[d] = 0.f;
#pragma unroll
    for (int s = 0; s < 32; s++) {
        float qq = qv[s];
#pragma unroll
        for (int d = 0; d < 32; d++) o[d] += qq * kvs[s][d];
    }
    __syncthreads();
#pragma unroll
    for (int d = 0; d < 32; d++) qs[tid][d] = o[d];
    __syncthreads();

    size_t obase = ((size_t)(b * Nq + n0)) * Cq + h * Dq;
#pragma unroll
    for (int i = 0; i < 32; i++) {
        int idx = tid + i * 128;
        int t = idx >> 5, d = idx & 31;
        qkvo[obase + (size_t)t * Cq + d] = qs[t][d];
    }
}

// ---------------------------- launcher ---------------------------------------
extern "C" void kernel_launch(void* const* d_in, const int* in_sizes, int n_in,
                              void* d_out, int out_size) {
    const float* fx   = (const float*)d_in[0];
    const float* ln1w = (const float*)d_in[1];
    const float* ln1b = (const float*)d_in[2];
    const float* Wx   = (const float*)d_in[3];
    const float* bx   = (const float*)d_in[4];
    const float* Wqp  = (const float*)d_in[5];
    const float* Wkp  = (const float*)d_in[6];
    const float* Wvp  = (const float*)d_in[7];
    const float* Wo   = (const float*)d_in[8];
    const float* bo   = (const float*)d_in[9];
    const float* ln2w = (const float*)d_in[10];
    const float* ln2b = (const float*)d_in[11];
    const float* W1   = (const float*)d_in[12];
    const float* b1   = (const float*)d_in[13];
    const float* W2   = (const float*)d_in[14];
    const float* b2   = (const float*)d_in[15];
    float* out = (float*)d_out;

    float *p_xln, *p_xmid, *p_q, *p_ek, *p_v, *p_qkv, *p_h, *p_y, *p_hid;
    cudaGetSymbolAddress((void**)&p_xln,  g_xln);
    cudaGetSymbolAddress((void**)&p_xmid, g_xmid);
    cudaGetSymbolAddress((void**)&p_q,    g_q);
    cudaGetSymbolAddress((void**)&p_ek,   g_ek);
    cudaGetSymbolAddress((void**)&p_v,    g_v);
    cudaGetSymbolAddress((void**)&p_qkv,  g_qkv);
    cudaGetSymbolAddress((void**)&p_h,    g_h);
    cudaGetSymbolAddress((void**)&p_y,    g_y);
    cudaGetSymbolAddress((void**)&p_hid,  g_hid);

    cudaFuncSetAttribute(tgemm_kernel<0>, cudaFuncAttributeMaxDynamicSharedMemorySize, GEMM_SMEM);
    cudaFuncSetAttribute(tgemm_kernel<1>, cudaFuncAttributeMaxDynamicSharedMemorySize, GEMM_SMEM);
    cudaFuncSetAttribute(tgemm_kernel<2>, cudaFuncAttributeMaxDynamicSharedMemorySize, GEMM_SMEM);

    dim3 lnBlk(32, 8);
    // 1) LN1
    ln_kernel<<<Mq / 8, lnBlk>>>(fx, ln1w, ln1b, p_xln);
    // 2) x_mid = xln @ Wx^T + bx   (mma.sync tf32)
    tgemm_kernel<0><<<dim3(Cq / BN, Mq / BM), 256, GEMM_SMEM>>>(p_xln, Wx, bx, nullptr, p_xmid, Cq, Cq);
    // 3) per-head q/k/v + softmaxes
    head_proj_kernel<<<dim3(Nq / 128, Hq, Bq), 128>>>(p_xmid, Wqp, Wkp, Wvp, p_q, p_ek, p_v);
    // 4) kv partial reduction
    ekv_reduce_kernel<<<dim3(KV_CHUNKS, Hq, Bq), 256>>>(p_ek, p_v);
    // 5) finalize kv
    kv_finalize_kernel<<<BHq, 256>>>();
    // 6) qkv = q @ kv
    qkv_apply_kernel<<<dim3(Nq / 128, Hq, Bq), 128>>>(p_q, p_qkv);
    // 7) h = qkv @ Wo^T + bo + fx
    tgemm_kernel<1><<<dim3(Cq / BN, Mq / BM), 256, GEMM_SMEM>>>(p_qkv, Wo, bo, fx, p_h, Cq, Cq);
    // 8) LN2
    ln_kernel<<<Mq / 8, lnBlk>>>(p_h, ln2w, ln2b, p_y);
    // 9) hid = gelu(y @ W1^T + b1)
    tgemm_kernel<2><<<dim3(HIDq / BN, Mq / BM), 256, GEMM_SMEM>>>(p_y, W1, b1, nullptr, p_hid, HIDq, Cq);
    // 10) out = hid @ W2^T + b2 + h
    tgemm_kernel<1><<<dim3(Cq / BN, Mq / BM), 256, GEMM_SMEM>>>(p_hid, W2, b2, p_h, out, Cq, HIDq);
}

// round 5
// speedup vs baseline: 4.3029x; 1.4845x over previous
#include <cuda_runtime.h>
#include <cuda_fp16.h>
#include <math.h>
#include <stdint.h>

// Problem constants
#define Bq   8
#define Nq   8192
#define Cq   256
#define Hq   8
#define Dq   32
#define Sq   32
#define HIDq 1024
#define Mq   (Bq * Nq)        // 65536 rows
#define BHq  (Bq * Hq)        // 64
#define KV_CHUNKS 16

// GEMM tiling (fp16 mma m16n8k16)
#define BM 128
#define BN 128
#define BKH 64                          // K-halves per tile (128 bytes/row)
#define STAGE_BYTES (2 * BM * BKH * 2)  // A tile + B tile = 32KB
#define GEMM_SMEM (2 * STAGE_BYTES)     // 2 stages = 64KB

// ---------------- scratch (static device arrays; no allocation) -------------
// NOTE: per-head buffers are BHq*Nq*Sq (= 16.8M floats), NOT Mq*Sq.
__device__ __half g_xln_h[Mq * Cq];
__device__ float  g_xmid [Mq * Cq];
__device__ float  g_q    [BHq * Nq * Sq];
__device__ float  g_ek   [BHq * Nq * Sq];
__device__ float  g_v    [BHq * Nq * Sq];
__device__ float  g_ekvp [KV_CHUNKS * BHq * Sq * Dq];
__device__ float  g_csp  [KV_CHUNKS * BHq * Sq];
__device__ float  g_kv   [BHq * Sq * Dq];
__device__ __half g_qkv_h[Mq * Cq];
__device__ float  g_h    [Mq * Cq];
__device__ __half g_y_h  [Mq * Cq];
__device__ __half g_hid_h[Mq * HIDq];
__device__ __half g_Wx_h [Cq * Cq];
__device__ __half g_Wo_h [Cq * Cq];
__device__ __half g_W1_h [HIDq * Cq];
__device__ __half g_W2_h [Cq * HIDq];

// ------------------------------ PTX helpers ---------------------------------
__device__ __forceinline__ uint32_t smem_u32(const void* p) {
    uint32_t a;
    asm("{ .reg .u64 t; cvta.to.shared.u64 t, %1; cvt.u32.u64 %0, t; }"
        : "=r"(a) : "l"(p));
    return a;
}
__device__ __forceinline__ void cp_async16(uint32_t dst, const void* src) {
    asm volatile("cp.async.ca.shared.global [%0], [%1], 16;"
                 :: "r"(dst), "l"(src));
}
__device__ __forceinline__ void cp_commit() {
    asm volatile("cp.async.commit_group;");
}
template <int N>
__device__ __forceinline__ void cp_wait() {
    asm volatile("cp.async.wait_group %0;" :: "n"(N));
}
__device__ __forceinline__ void ldsm4(uint32_t* r, uint32_t addr) {
    asm volatile("ldmatrix.sync.aligned.m8n8.x4.shared.b16 {%0,%1,%2,%3}, [%4];"
                 : "=r"(r[0]), "=r"(r[1]), "=r"(r[2]), "=r"(r[3]) : "r"(addr));
}
__device__ __forceinline__ void mma_f16(float* c, const uint32_t* a, const uint32_t* b) {
    asm volatile(
        "mma.sync.aligned.m16n8k16.row.col.f32.f16.f16.f32 "
        "{%0,%1,%2,%3}, {%4,%5,%6,%7}, {%8,%9}, {%0,%1,%2,%3};"
        : "+f"(c[0]), "+f"(c[1]), "+f"(c[2]), "+f"(c[3])
        : "r"(a[0]), "r"(a[1]), "r"(a[2]), "r"(a[3]), "r"(b[0]), "r"(b[1]));
}

// ---------------- fp32 -> fp16 weight conversion -----------------------------
__global__ void f2h_kernel(const float* __restrict__ src, __half* __restrict__ dst, int n4) {
    int i = blockIdx.x * 256 + threadIdx.x;
    if (i < n4) {
        float4 v = ((const float4*)src)[i];
        ((__half2*)dst)[i * 2]     = __floats2half2_rn(v.x, v.y);
        ((__half2*)dst)[i * 2 + 1] = __floats2half2_rn(v.z, v.w);
    }
}

// ---------------- LayerNorm: one warp per row (C=256), fp16 out -------------
__global__ void ln_kernel(const float* __restrict__ x,
                          const float* __restrict__ w,
                          const float* __restrict__ bb,
                          __half* __restrict__ out) {
    int row  = blockIdx.x * 8 + threadIdx.y;
    int lane = threadIdx.x;
    const float* xr = x + (size_t)row * Cq;
    float v[8];
    float s = 0.f, s2 = 0.f;
#pragma unroll
    for (int i = 0; i < 8; i++) {
        float t = xr[lane + i * 32];
        v[i] = t; s += t; s2 += t * t;
    }
#pragma unroll
    for (int o = 16; o > 0; o >>= 1) {
        s  += __shfl_xor_sync(0xffffffffu, s,  o);
        s2 += __shfl_xor_sync(0xffffffffu, s2, o);
    }
    float mu  = s * (1.f / Cq);
    float var = s2 * (1.f / Cq) - mu * mu;
    float rs  = rsqrtf(var + 1e-5f);
    __half* orow = out + (size_t)row * Cq;
#pragma unroll
    for (int i = 0; i < 8; i++) {
        int c = lane + i * 32;
        orow[c] = __float2half_rn((v[i] - mu) * rs * w[c] + bb[c]);
    }
}

// ------------- fp16 mma GEMM: C = A[M,K] @ W[Ncols,K]^T + bias --------------
// EPI: 0 = bias, 1 = bias + residual, 2 = bias + exact GELU
// OUT16: write fp16 output instead of fp32
__device__ __forceinline__ float gelu_exact(float v) {
    return 0.5f * v * (1.f + erff(v * 0.70710678118654752f));
}

template <int EPI, int OUT16>
__global__ __launch_bounds__(256) void hgemm_kernel(
    const __half* __restrict__ A, const __half* __restrict__ W,
    const float* __restrict__ bias, const float* __restrict__ res,
    float* __restrict__ Cout, __half* __restrict__ Cout16,
    int Ncols, int K) {
    extern __shared__ char smem[];
    int tid  = threadIdx.x;
    int wid  = tid >> 5, lane = tid & 31;
    int g = lane >> 2, q = lane & 3;
    int warp_m = wid >> 2;        // 0..1 -> 64 rows
    int warp_n = wid & 3;         // 0..3 -> 32 cols

    uint32_t sbase = smem_u32(smem);
    const __half* Ab = A + (size_t)blockIdx.y * BM * K;
    const __half* Wb = W + (size_t)blockIdx.x * BN * K;

    float acc[4][4][4];
#pragma unroll
    for (int mt = 0; mt < 4; mt++)
#pragma unroll
        for (int nt = 0; nt < 4; nt++)
#pragma unroll
            for (int i = 0; i < 4; i++) acc[mt][nt][i] = 0.f;

    int ntiles = K / BKH;

    auto load_tile = [&](int stage, int kt) {
        uint32_t aoff = sbase + stage * STAGE_BYTES;
        uint32_t boff = aoff + BM * BKH * 2;
        int k0 = kt * BKH;
#pragma unroll
        for (int i = 0; i < 4; i++) {
            int idx  = i * 256 + tid;
            int row  = idx >> 3;
            int grp  = idx & 7;
            int phys = grp ^ (row & 7);
            cp_async16(aoff + (row * 8 + phys) * 16, &Ab[(size_t)row * K + k0 + grp * 8]);
            cp_async16(boff + (row * 8 + phys) * 16, &Wb[(size_t)row * K + k0 + grp * 8]);
        }
    };

    load_tile(0, 0);
    cp_commit();

    for (int kt = 0; kt < ntiles; kt++) {
        int cur = kt & 1;
        if (kt + 1 < ntiles) {
            load_tile(cur ^ 1, kt + 1);
            cp_commit();
            cp_wait<1>();
        } else {
            cp_wait<0>();
        }
        __syncthreads();

        uint32_t sA = sbase + cur * STAGE_BYTES;
        uint32_t sB = sA + BM * BKH * 2;

#pragma unroll
        for (int ks = 0; ks < 4; ks++) {
            uint32_t af[4][4];
#pragma unroll
            for (int mt = 0; mt < 4; mt++) {
                int row = warp_m * 64 + mt * 16 + (lane & 15);
                int kg  = 2 * ks + (lane >> 4);
                ldsm4(af[mt], sA + (row * 8 + (kg ^ (row & 7))) * 16);
            }
            uint32_t bf[2][4];
#pragma unroll
            for (int p = 0; p < 2; p++) {
                int n  = warp_n * 32 + p * 16 + (lane >> 4) * 8 + (lane & 7);
                int kg = 2 * ks + ((lane >> 3) & 1);
                ldsm4(bf[p], sB + (n * 8 + (kg ^ (n & 7))) * 16);
            }
#pragma unroll
            for (int mt = 0; mt < 4; mt++)
#pragma unroll
                for (int nt = 0; nt < 4; nt++)
                    mma_f16(acc[mt][nt], af[mt], &bf[nt >> 1][(nt & 1) * 2]);
        }
        __syncthreads();
    }

    // Epilogue: direct register -> global
    int mBase = blockIdx.y * BM + warp_m * 64;
    int nBase = blockIdx.x * BN + warp_n * 32;
#pragma unroll
    for (int nt = 0; nt < 4; nt++) {
        int c0 = nBase + nt * 8 + q * 2;
        float bv0 = bias[c0], bv1 = bias[c0 + 1];
#pragma unroll
        for (int mt = 0; mt < 4; mt++) {
            int r0 = mBase + mt * 16 + g;
#pragma unroll
            for (int half = 0; half < 2; half++) {
                int r = r0 + half * 8;
                size_t off = (size_t)r * Ncols + c0;
                float v0 = acc[mt][nt][half * 2 + 0] + bv0;
                float v1 = acc[mt][nt][half * 2 + 1] + bv1;
                if (EPI == 1) {
                    float2 rr = *(const float2*)&res[off];
                    v0 += rr.x; v1 += rr.y;
                }
                if (EPI == 2) { v0 = gelu_exact(v0); v1 = gelu_exact(v1); }
                if (OUT16) {
                    *(__half2*)&Cout16[off] = __floats2half2_rn(v0, v1);
                } else {
                    *(float2*)&Cout[off] = make_float2(v0, v1);
                }
            }
        }
    }
}

// ------------- per-head q/k/v projection + softmaxes (fused) ----------------
__global__ __launch_bounds__(128) void head_proj_kernel(
    const float* __restrict__ xmid,
    const float* __restrict__ Wq, const float* __restrict__ Wk,
    const float* __restrict__ Wv,
    float* __restrict__ qo, float* __restrict__ eko, float* __restrict__ vo) {
    __shared__ float xs[128][33];
    __shared__ float wq[Sq * Dq], wk[Sq * Dq], wv[Dq * Dq];
    int tid = threadIdx.x;
    int h = blockIdx.y, b = blockIdx.z;
    int n0 = blockIdx.x * 128;

#pragma unroll
    for (int i = 0; i < 8; i++) {
        int idx = tid + i * 128;
        wq[idx] = Wq[idx]; wk[idx] = Wk[idx]; wv[idx] = Wv[idx];
    }
    size_t base = ((size_t)(b * Nq + n0)) * Cq + h * Dq;
#pragma unroll
    for (int i = 0; i < 32; i++) {
        int idx = tid + i * 128;
        int t = idx >> 5, d = idx & 31;
        xs[t][d] = xmid[base + (size_t)t * Cq + d];
    }
    __syncthreads();

    float x[32];
#pragma unroll
    for (int d = 0; d < 32; d++) x[d] = xs[tid][d];
    __syncthreads();

    size_t obase = ((size_t)((b * Hq + h) * (size_t)Nq + n0)) * 32;

    {
        float e[32]; float ssum = 0.f;
#pragma unroll
        for (int s = 0; s < 32; s++) {
            float a = 0.f;
#pragma unroll
            for (int d = 0; d < 32; d++) a += x[d] * wq[s * 32 + d];
            e[s] = expf(a); ssum += e[s];
        }
        float r = 1.f / ssum;
#pragma unroll
        for (int s = 0; s < 32; s++) xs[tid][s] = e[s] * r;
        __syncthreads();
#pragma unroll
        for (int i = 0; i < 32; i++) {
            int idx = tid + i * 128;
            qo[obase + idx] = xs[idx >> 5][idx & 31];
        }
        __syncthreads();
    }
    {
#pragma unroll
        for (int s = 0; s < 32; s++) {
            float a = 0.f;
#pragma unroll
            for (int d = 0; d < 32; d++) a += x[d] * wk[s * 32 + d];
            xs[tid][s] = expf(a);
        }
        __syncthreads();
#pragma unroll
        for (int i = 0; i < 32; i++) {
            int idx = tid + i * 128;
            eko[obase + idx] = xs[idx >> 5][idx & 31];
        }
        __syncthreads();
    }
    {
#pragma unroll
        for (int dp = 0; dp < 32; dp++) {
            float a = 0.f;
#pragma unroll
            for (int d = 0; d < 32; d++) a += x[d] * wv[dp * 32 + d];
            xs[tid][dp] = a;
        }
        __syncthreads();
#pragma unroll
        for (int i = 0; i < 32; i++) {
            int idx = tid + i * 128;
            vo[obase + idx] = xs[idx >> 5][idx & 31];
        }
    }
}

// ---------- kv partial reduction: ekv[s,d] = sum_n ek[n,s]*v[n,d] ------------
__global__ __launch_bounds__(256) void ekv_reduce_kernel(
    const float* __restrict__ ek, const float* __restrict__ v) {
    int tid = threadIdx.x;
    int s = tid & 31;
    int d0 = (tid >> 5) * 4;
    int h = blockIdx.y, b = blockIdx.z;
    int bh = b * Hq + h;
    int ch = blockIdx.x;
    int n0 = ch * (Nq / KV_CHUNKS);

    __shared__ float es[64][33], vs[64][33];
    float a0 = 0.f, a1 = 0.f, a2 = 0.f, a3 = 0.f, cs = 0.f;
    size_t base = ((size_t)bh * Nq + n0) * 32;

    for (int t0 = 0; t0 < Nq / KV_CHUNKS; t0 += 64) {
#pragma unroll
        for (int i = 0; i < 8; i++) {
            int idx = tid + i * 256;
            int t = idx >> 5, dd = idx & 31;
            es[t][dd] = ek[base + (size_t)(t0 + t) * 32 + dd];
            vs[t][dd] = v [base + (size_t)(t0 + t) * 32 + dd];
        }
        __syncthreads();
#pragma unroll 4
        for (int t = 0; t < 64; t++) {
            float e = es[t][s];
            cs += e;
            a0 += e * vs[t][d0 + 0];
            a1 += e * vs[t][d0 + 1];
            a2 += e * vs[t][d0 + 2];
            a3 += e * vs[t][d0 + 3];
        }
        __syncthreads();
    }
    float* ep = &g_ekvp[((size_t)ch * BHq + bh) * (Sq * Dq) + s * 32 + d0];
    ep[0] = a0; ep[1] = a1; ep[2] = a2; ep[3] = a3;
    if (d0 == 0) g_csp[((size_t)ch * BHq + bh) * Sq + s] = cs;
}

// ---------- kv finalize: sum chunks deterministically, normalize ------------
__global__ void kv_finalize_kernel() {
    int bh = blockIdx.x;
    int tid = threadIdx.x;
    __shared__ float rcs[32];
    if (tid < 32) {
        float c = 0.f;
#pragma unroll
        for (int ch = 0; ch < KV_CHUNKS; ch++)
            c += g_csp[((size_t)ch * BHq + bh) * Sq + tid];
        rcs[tid] = 1.f / c;
    }
    __syncthreads();
    for (int idx = tid; idx < Sq * Dq; idx += blockDim.x) {
        float vsum = 0.f;
#pragma unroll
        for (int ch = 0; ch < KV_CHUNKS; ch++)
            vsum += g_ekvp[((size_t)ch * BHq + bh) * (Sq * Dq) + idx];
        g_kv[(size_t)bh * (Sq * Dq) + idx] = vsum * rcs[idx >> 5];
    }
}

// ---------- qkv = q @ kv, concat heads back into [B,N,C] (fp16 out) ---------
__global__ __launch_bounds__(128) void qkv_apply_kernel(
    const float* __restrict__ q, __half* __restrict__ qkvo) {
    __shared__ float qs[128][33];
    __shared__ float kvs[32][33];
    int tid = threadIdx.x;
    int h = blockIdx.y, b = blockIdx.z, bh = b * Hq + h;
    int n0 = blockIdx.x * 128;

#pragma unroll
    for (int i = 0; i < 8; i++) {
        int idx = tid + i * 128;
        kvs[idx >> 5][idx & 31] = g_kv[(size_t)bh * (Sq * Dq) + idx];
    }
    size_t qbase = ((size_t)bh * Nq + n0) * 32;
#pragma unroll
    for (int i = 0; i < 32; i++) {
        int idx = tid + i * 128;
        qs[idx >> 5][idx & 31] = q[qbase + idx];
    }
    __syncthreads();

    float qv[32];
#pragma unroll
    for (int s = 0; s < 32; s++) qv[s] = qs[tid][s];
    float o[32];
#pragma unroll
    for (int d = 0; d < 32; d++) o[d] = 0.f;
#pragma unroll
    for (int s = 0; s < 32; s++) {
        float qq = qv[s];
#pragma unroll
        for (int d = 0; d < 32; d++) o[d] += qq * kvs[s][d];
    }
    __syncthreads();
#pragma unroll
    for (int d = 0; d < 32; d++) qs[tid][d] = o[d];
    __syncthreads();

    size_t obase = ((size_t)(b * Nq + n0)) * Cq + h * Dq;
#pragma unroll
    for (int i = 0; i < 32; i++) {
        int idx = tid + i * 128;
        int t = idx >> 5, d = idx & 31;
        qkvo[obase + (size_t)t * Cq + d] = __float2half_rn(qs[t][d]);
    }
}

// ---------------------------- launcher ---------------------------------------
extern "C" void kernel_launch(void* const* d_in, const int* in_sizes, int n_in,
                              void* d_out, int out_size) {
    const float* fx   = (const float*)d_in[0];
    const float* ln1w = (const float*)d_in[1];
    const float* ln1b = (const float*)d_in[2];
    const float* Wx   = (const float*)d_in[3];
    const float* bx   = (const float*)d_in[4];
    const float* Wqp  = (const float*)d_in[5];
    const float* Wkp  = (const float*)d_in[6];
    const float* Wvp  = (const float*)d_in[7];
    const float* Wo   = (const float*)d_in[8];
    const float* bo   = (const float*)d_in[9];
    const float* ln2w = (const float*)d_in[10];
    const float* ln2b = (const float*)d_in[11];
    const float* W1   = (const float*)d_in[12];
    const float* b1   = (const float*)d_in[13];
    const float* W2   = (const float*)d_in[14];
    const float* b2   = (const float*)d_in[15];
    float* out = (float*)d_out;

    __half *p_xln, *p_qkv, *p_y, *p_hid, *p_Wx, *p_Wo, *p_W1, *p_W2;
    float  *p_xmid, *p_q, *p_ek, *p_v, *p_h;
    cudaGetSymbolAddress((void**)&p_xln,  g_xln_h);
    cudaGetSymbolAddress((void**)&p_xmid, g_xmid);
    cudaGetSymbolAddress((void**)&p_q,    g_q);
    cudaGetSymbolAddress((void**)&p_ek,   g_ek);
    cudaGetSymbolAddress((void**)&p_v,    g_v);
    cudaGetSymbolAddress((void**)&p_qkv,  g_qkv_h);
    cudaGetSymbolAddress((void**)&p_h,    g_h);
    cudaGetSymbolAddress((void**)&p_y,    g_y_h);
    cudaGetSymbolAddress((void**)&p_hid,  g_hid_h);
    cudaGetSymbolAddress((void**)&p_Wx,   g_Wx_h);
    cudaGetSymbolAddress((void**)&p_Wo,   g_Wo_h);
    cudaGetSymbolAddress((void**)&p_W1,   g_W1_h);
    cudaGetSymbolAddress((void**)&p_W2,   g_W2_h);

    cudaFuncSetAttribute(hgemm_kernel<0,0>, cudaFuncAttributeMaxDynamicSharedMemorySize, GEMM_SMEM);
    cudaFuncSetAttribute(hgemm_kernel<1,0>, cudaFuncAttributeMaxDynamicSharedMemorySize, GEMM_SMEM);
    cudaFuncSetAttribute(hgemm_kernel<2,1>, cudaFuncAttributeMaxDynamicSharedMemorySize, GEMM_SMEM);

    // 0) weight conversion fp32 -> fp16
    f2h_kernel<<<(Cq * Cq / 4 + 255) / 256, 256>>>(Wx, p_Wx, Cq * Cq / 4);
    f2h_kernel<<<(Cq * Cq / 4 + 255) / 256, 256>>>(Wo, p_Wo, Cq * Cq / 4);
    f2h_kernel<<<(HIDq * Cq / 4 + 255) / 256, 256>>>(W1, p_W1, HIDq * Cq / 4);
    f2h_kernel<<<(Cq * HIDq / 4 + 255) / 256, 256>>>(W2, p_W2, Cq * HIDq / 4);

    dim3 lnBlk(32, 8);
    // 1) LN1 -> fp16
    ln_kernel<<<Mq / 8, lnBlk>>>(fx, ln1w, ln1b, p_xln);
    // 2) x_mid = xln @ Wx^T + bx  (fp16 mma, fp32 out)
    hgemm_kernel<0,0><<<dim3(Cq / BN, Mq / BM), 256, GEMM_SMEM>>>(
        p_xln, p_Wx, bx, nullptr, p_xmid, nullptr, Cq, Cq);
    // 3) per-head q/k/v + softmaxes
    head_proj_kernel<<<dim3(Nq / 128, Hq, Bq), 128>>>(p_xmid, Wqp, Wkp, Wvp, p_q, p_ek, p_v);
    // 4) kv partial reduction
    ekv_reduce_kernel<<<dim3(KV_CHUNKS, Hq, Bq), 256>>>(p_ek, p_v);
    // 5) finalize kv
    kv_finalize_kernel<<<BHq, 256>>>();
    // 6) qkv = q @ kv  (fp16 out)
    qkv_apply_kernel<<<dim3(Nq / 128, Hq, Bq), 128>>>(p_q, p_qkv);
    // 7) h = qkv @ Wo^T + bo + fx  (fp32 out)
    hgemm_kernel<1,0><<<dim3(Cq / BN, Mq / BM), 256, GEMM_SMEM>>>(
        p_qkv, p_Wo, bo, fx, p_h, nullptr, Cq, Cq);
    // 8) LN2 -> fp16
    ln_kernel<<<Mq / 8, lnBlk>>>(p_h, ln2w, ln2b, p_y);
    // 9) hid = gelu(y @ W1^T + b1)  (fp16 out)
    hgemm_kernel<2,1><<<dim3(HIDq / BN, Mq / BM), 256, GEMM_SMEM>>>(
        p_y, p_W1, b1, nullptr, nullptr, p_hid, HIDq, Cq);
    // 10) out = hid @ W2^T + b2 + h  (fp32 out)
    hgemm_kernel<1,0><<<dim3(Cq / BN, Mq / BM), 256, GEMM_SMEM>>>(
        p_hid, p_W2, b2, p_h, out, nullptr, Cq, HIDq);
}

// round 6
// speedup vs baseline: 4.5473x; 1.0568x over previous
#include <cuda_runtime.h>
#include <cuda_fp16.h>
#include <math.h>
#include <stdint.h>

// Problem constants
#define Bq   8
#define Nq   8192
#define Cq   256
#define Hq   8
#define Dq   32
#define Sq   32
#define HIDq 1024
#define Mq   (Bq * Nq)        // 65536 rows
#define BHq  (Bq * Hq)        // 64
#define KV_CHUNKS 64          // one chunk per 128-token head_proj CTA

// GEMM tiling (fp16 mma m16n8k16)
#define BM 128
#define BN 128
#define BKH 64                          // K-halves per tile (128 bytes/row)
#define STAGE_BYTES (2 * BM * BKH * 2)  // A tile + B tile = 32KB
#define GEMM_SMEM (2 * STAGE_BYTES)     // 2 stages = 64KB

// ---------------- scratch (static device arrays; no allocation) -------------
__device__ __half g_xln_h[Mq * Cq];
__device__ float  g_xmid [Mq * Cq];
__device__ __half g_q_h  [(size_t)BHq * Nq * Sq];
__device__ float  g_ekvp [KV_CHUNKS * BHq * Sq * Dq];   // per-chunk partial kv
__device__ float  g_csp  [KV_CHUNKS * BHq * Sq];        // per-chunk col sums
__device__ float  g_kv   [BHq * Sq * Dq];
__device__ __half g_qkv_h[Mq * Cq];
__device__ float  g_h    [Mq * Cq];
__device__ __half g_y_h  [Mq * Cq];
__device__ __half g_hid_h[Mq * HIDq];
__device__ __half g_Wx_h [Cq * Cq];
__device__ __half g_Wo_h [Cq * Cq];
__device__ __half g_W1_h [HIDq * Cq];
__device__ __half g_W2_h [Cq * HIDq];

// ------------------------------ PTX helpers ---------------------------------
__device__ __forceinline__ uint32_t smem_u32(const void* p) {
    uint32_t a;
    asm("{ .reg .u64 t; cvta.to.shared.u64 t, %1; cvt.u32.u64 %0, t; }"
        : "=r"(a) : "l"(p));
    return a;
}
__device__ __forceinline__ void cp_async16(uint32_t dst, const void* src) {
    asm volatile("cp.async.ca.shared.global [%0], [%1], 16;"
                 :: "r"(dst), "l"(src));
}
__device__ __forceinline__ void cp_commit() {
    asm volatile("cp.async.commit_group;");
}
template <int N>
__device__ __forceinline__ void cp_wait() {
    asm volatile("cp.async.wait_group %0;" :: "n"(N));
}
__device__ __forceinline__ void ldsm4(uint32_t* r, uint32_t addr) {
    asm volatile("ldmatrix.sync.aligned.m8n8.x4.shared.b16 {%0,%1,%2,%3}, [%4];"
                 : "=r"(r[0]), "=r"(r[1]), "=r"(r[2]), "=r"(r[3]) : "r"(addr));
}
__device__ __forceinline__ void mma_f16(float* c, const uint32_t* a, const uint32_t* b) {
    asm volatile(
        "mma.sync.aligned.m16n8k16.row.col.f32.f16.f16.f32 "
        "{%0,%1,%2,%3}, {%4,%5,%6,%7}, {%8,%9}, {%0,%1,%2,%3};"
        : "+f"(c[0]), "+f"(c[1]), "+f"(c[2]), "+f"(c[3])
        : "r"(a[0]), "r"(a[1]), "r"(a[2]), "r"(a[3]), "r"(b[0]), "r"(b[1]));
}

// ---------------- fp32 -> fp16 weight conversion -----------------------------
__global__ void f2h_kernel(const float* __restrict__ src, __half* __restrict__ dst, int n4) {
    int i = blockIdx.x * 256 + threadIdx.x;
    if (i < n4) {
        float4 v = ((const float4*)src)[i];
        ((__half2*)dst)[i * 2]     = __floats2half2_rn(v.x, v.y);
        ((__half2*)dst)[i * 2 + 1] = __floats2half2_rn(v.z, v.w);
    }
}

// ---------------- LayerNorm: one warp per row (C=256), fp16 out -------------
__global__ void ln_kernel(const float* __restrict__ x,
                          const float* __restrict__ w,
                          const float* __restrict__ bb,
                          __half* __restrict__ out) {
    int row  = blockIdx.x * 8 + threadIdx.y;
    int lane = threadIdx.x;
    const float* xr = x + (size_t)row * Cq;
    float v[8];
    float s = 0.f, s2 = 0.f;
#pragma unroll
    for (int i = 0; i < 8; i++) {
        float t = xr[lane + i * 32];
        v[i] = t; s += t; s2 += t * t;
    }
#pragma unroll
    for (int o = 16; o > 0; o >>= 1) {
        s  += __shfl_xor_sync(0xffffffffu, s,  o);
        s2 += __shfl_xor_sync(0xffffffffu, s2, o);
    }
    float mu  = s * (1.f / Cq);
    float var = s2 * (1.f / Cq) - mu * mu;
    float rs  = rsqrtf(var + 1e-5f);
    __half* orow = out + (size_t)row * Cq;
#pragma unroll
    for (int i = 0; i < 8; i++) {
        int c = lane + i * 32;
        orow[c] = __float2half_rn((v[i] - mu) * rs * w[c] + bb[c]);
    }
}

// ------------- fp16 mma GEMM: C = A[M,K] @ W[Ncols,K]^T + bias --------------
__device__ __forceinline__ float gelu_exact(float v) {
    return 0.5f * v * (1.f + erff(v * 0.70710678118654752f));
}

template <int EPI, int OUT16>
__global__ __launch_bounds__(256) void hgemm_kernel(
    const __half* __restrict__ A, const __half* __restrict__ W,
    const float* __restrict__ bias, const float* __restrict__ res,
    float* __restrict__ Cout, __half* __restrict__ Cout16,
    int Ncols, int K) {
    extern __shared__ char smem[];
    int tid  = threadIdx.x;
    int wid  = tid >> 5, lane = tid & 31;
    int g = lane >> 2, q = lane & 3;
    int warp_m = wid >> 2;
    int warp_n = wid & 3;

    uint32_t sbase = smem_u32(smem);
    const __half* Ab = A + (size_t)blockIdx.y * BM * K;
    const __half* Wb = W + (size_t)blockIdx.x * BN * K;

    float acc[4][4][4];
#pragma unroll
    for (int mt = 0; mt < 4; mt++)
#pragma unroll
        for (int nt = 0; nt < 4; nt++)
#pragma unroll
            for (int i = 0; i < 4; i++) acc[mt][nt][i] = 0.f;

    int ntiles = K / BKH;

    auto load_tile = [&](int stage, int kt) {
        uint32_t aoff = sbase + stage * STAGE_BYTES;
        uint32_t boff = aoff + BM * BKH * 2;
        int k0 = kt * BKH;
#pragma unroll
        for (int i = 0; i < 4; i++) {
            int idx  = i * 256 + tid;
            int row  = idx >> 3;
            int grp  = idx & 7;
            int phys = grp ^ (row & 7);
            cp_async16(aoff + (row * 8 + phys) * 16, &Ab[(size_t)row * K + k0 + grp * 8]);
            cp_async16(boff + (row * 8 + phys) * 16, &Wb[(size_t)row * K + k0 + grp * 8]);
        }
    };

    load_tile(0, 0);
    cp_commit();

    for (int kt = 0; kt < ntiles; kt++) {
        int cur = kt & 1;
        if (kt + 1 < ntiles) {
            load_tile(cur ^ 1, kt + 1);
            cp_commit();
            cp_wait<1>();
        } else {
            cp_wait<0>();
        }
        __syncthreads();

        uint32_t sA = sbase + cur * STAGE_BYTES;
        uint32_t sB = sA + BM * BKH * 2;

#pragma unroll
        for (int ks = 0; ks < 4; ks++) {
            uint32_t af[4][4];
#pragma unroll
            for (int mt = 0; mt < 4; mt++) {
                int row = warp_m * 64 + mt * 16 + (lane & 15);
                int kg  = 2 * ks + (lane >> 4);
                ldsm4(af[mt], sA + (row * 8 + (kg ^ (row & 7))) * 16);
            }
            uint32_t bf[2][4];
#pragma unroll
            for (int p = 0; p < 2; p++) {
                int n  = warp_n * 32 + p * 16 + (lane >> 4) * 8 + (lane & 7);
                int kg = 2 * ks + ((lane >> 3) & 1);
                ldsm4(bf[p], sB + (n * 8 + (kg ^ (n & 7))) * 16);
            }
#pragma unroll
            for (int mt = 0; mt < 4; mt++)
#pragma unroll
                for (int nt = 0; nt < 4; nt++)
                    mma_f16(acc[mt][nt], af[mt], &bf[nt >> 1][(nt & 1) * 2]);
        }
        __syncthreads();
    }

    int mBase = blockIdx.y * BM + warp_m * 64;
    int nBase = blockIdx.x * BN + warp_n * 32;
#pragma unroll
    for (int nt = 0; nt < 4; nt++) {
        int c0 = nBase + nt * 8 + q * 2;
        float bv0 = bias[c0], bv1 = bias[c0 + 1];
#pragma unroll
        for (int mt = 0; mt < 4; mt++) {
            int r0 = mBase + mt * 16 + g;
#pragma unroll
            for (int half = 0; half < 2; half++) {
                int r = r0 + half * 8;
                size_t off = (size_t)r * Ncols + c0;
                float v0 = acc[mt][nt][half * 2 + 0] + bv0;
                float v1 = acc[mt][nt][half * 2 + 1] + bv1;
                if (EPI == 1) {
                    float2 rr = *(const float2*)&res[off];
                    v0 += rr.x; v1 += rr.y;
                }
                if (EPI == 2) { v0 = gelu_exact(v0); v1 = gelu_exact(v1); }
                if (OUT16) {
                    *(__half2*)&Cout16[off] = __floats2half2_rn(v0, v1);
                } else {
                    *(float2*)&Cout[off] = make_float2(v0, v1);
                }
            }
        }
    }
}

// ------- fused per-head projection + softmaxes + partial kv reduction -------
// block = 128 tokens of one (b,h); thread = one token.
// Outputs: q (fp16, global), partial kv (32x32) + col sums for this chunk.
__global__ __launch_bounds__(128) void head_proj_fused_kernel(
    const float* __restrict__ xmid,
    const float* __restrict__ Wq, const float* __restrict__ Wk,
    const float* __restrict__ Wv,
    __half* __restrict__ qo) {
    __shared__ float xs[128][33];   // x tile; reused for ek after x -> regs
    __shared__ float vs[128][33];   // v tile
    __shared__ float wq[Sq * Dq], wk[Sq * Dq], wv[Dq * Dq];
    int tid = threadIdx.x;
    int h = blockIdx.y, b = blockIdx.z;
    int ch = blockIdx.x;            // chunk index == n0/128
    int n0 = ch * 128;
    int bh = b * Hq + h;

#pragma unroll
    for (int i = 0; i < 8; i++) {
        int idx = tid + i * 128;
        wq[idx] = Wq[idx]; wk[idx] = Wk[idx]; wv[idx] = Wv[idx];
    }
    size_t base = ((size_t)(b * Nq + n0)) * Cq + h * Dq;
#pragma unroll
    for (int i = 0; i < 32; i++) {
        int idx = tid + i * 128;
        int t = idx >> 5, d = idx & 31;
        xs[t][d] = xmid[base + (size_t)t * Cq + d];
    }
    __syncthreads();

    float x[32];
#pragma unroll
    for (int d = 0; d < 32; d++) x[d] = xs[tid][d];
    __syncthreads();   // all threads have x in regs; xs now reusable

    // --- q = softmax_s(x @ Wq^T), written fp16 straight to global ---
    {
        float e[32]; float ssum = 0.f;
#pragma unroll
        for (int s = 0; s < 32; s++) {
            float a = 0.f;
#pragma unroll
            for (int d = 0; d < 32; d++) a += x[d] * wq[s * 32 + d];
            e[s] = expf(a); ssum += e[s];
        }
        float r = 1.f / ssum;
        __half2 qh[16];
#pragma unroll
        for (int s = 0; s < 16; s++)
            qh[s] = __floats2half2_rn(e[2 * s] * r, e[2 * s + 1] * r);
        size_t qoff = ((size_t)bh * Nq + n0 + tid) * 32;
        uint4* dst = (uint4*)(qo + qoff);
#pragma unroll
        for (int i = 0; i < 4; i++) dst[i] = ((uint4*)qh)[i];
    }

    // --- ek = exp(x @ Wk^T) -> xs;  v = x @ Wv^T -> vs ---
#pragma unroll
    for (int s = 0; s < 32; s++) {
        float a = 0.f;
#pragma unroll
        for (int d = 0; d < 32; d++) a += x[d] * wk[s * 32 + d];
        xs[tid][s] = expf(a);
    }
#pragma unroll
    for (int dp = 0; dp < 32; dp++) {
        float a = 0.f;
#pragma unroll
        for (int d = 0; d < 32; d++) a += x[d] * wv[dp * 32 + d];
        vs[tid][dp] = a;
    }
    __syncthreads();

    // --- partial kv: a[s][d] = sum_t ek[t][s] * v[t][d] over 128 tokens ---
    int s  = tid & 31;
    int d0 = (tid >> 5) * 8;     // 4 warps x 8 d's = 32 d
    float a[8];
#pragma unroll
    for (int j = 0; j < 8; j++) a[j] = 0.f;
    float cs = 0.f;
#pragma unroll 4
    for (int t = 0; t < 128; t++) {
        float e = xs[t][s];
        cs += e;
#pragma unroll
        for (int j = 0; j < 8; j++) a[j] += e * vs[t][d0 + j];
    }
    float* ep = &g_ekvp[((size_t)ch * BHq + bh) * (Sq * Dq) + s * 32 + d0];
#pragma unroll
    for (int j = 0; j < 8; j++) ep[j] = a[j];
    if (tid < 32) g_csp[((size_t)ch * BHq + bh) * Sq + s] = cs;
}

// ---------- kv finalize: sum chunks deterministically, normalize ------------
__global__ void kv_finalize_kernel() {
    int bh = blockIdx.x;
    int tid = threadIdx.x;
    __shared__ float rcs[32];
    if (tid < 32) {
        float c = 0.f;
#pragma unroll
        for (int ch = 0; ch < KV_CHUNKS; ch++)
            c += g_csp[((size_t)ch * BHq + bh) * Sq + tid];
        rcs[tid] = 1.f / c;
    }
    __syncthreads();
    for (int idx = tid; idx < Sq * Dq; idx += blockDim.x) {
        float vsum = 0.f;
#pragma unroll
        for (int ch = 0; ch < KV_CHUNKS; ch++)
            vsum += g_ekvp[((size_t)ch * BHq + bh) * (Sq * Dq) + idx];
        g_kv[(size_t)bh * (Sq * Dq) + idx] = vsum * rcs[idx >> 5];
    }
}

// ---------- qkv = q @ kv, concat heads back into [B,N,C] (fp16 in/out) ------
__global__ __launch_bounds__(128) void qkv_apply_kernel(
    const __half* __restrict__ q, __half* __restrict__ qkvo) {
    __shared__ float qs[128][33];
    __shared__ float kvs[32][33];
    int tid = threadIdx.x;
    int h = blockIdx.y, b = blockIdx.z, bh = b * Hq + h;
    int n0 = blockIdx.x * 128;

#pragma unroll
    for (int i = 0; i < 8; i++) {
        int idx = tid + i * 128;
        kvs[idx >> 5][idx & 31] = g_kv[(size_t)bh * (Sq * Dq) + idx];
    }
    size_t qbase = ((size_t)bh * Nq + n0) * 32;
#pragma unroll
    for (int i = 0; i < 32; i++) {
        int idx = tid + i * 128;
        qs[idx >> 5][idx & 31] = __half2float(q[qbase + idx]);
    }
    __syncthreads();

    float qv[32];
#pragma unroll
    for (int s = 0; s < 32; s++) qv[s] = qs[tid][s];
    float o[32];
#pragma unroll
    for (int d = 0; d < 32; d++) o[d] = 0.f;
#pragma unroll
    for (int s = 0; s < 32; s++) {
        float qq = qv[s];
#pragma unroll
        for (int d = 0; d < 32; d++) o[d] += qq * kvs[s][d];
    }
    __syncthreads();
#pragma unroll
    for (int d = 0; d < 32; d++) qs[tid][d] = o[d];
    __syncthreads();

    size_t obase = ((size_t)(b * Nq + n0)) * Cq + h * Dq;
#pragma unroll
    for (int i = 0; i < 32; i++) {
        int idx = tid + i * 128;
        int t = idx >> 5, d = idx & 31;
        qkvo[obase + (size_t)t * Cq + d] = __float2half_rn(qs[t][d]);
    }
}

// ---------------------------- launcher ---------------------------------------
extern "C" void kernel_launch(void* const* d_in, const int* in_sizes, int n_in,
                              void* d_out, int out_size) {
    const float* fx   = (const float*)d_in[0];
    const float* ln1w = (const float*)d_in[1];
    const float* ln1b = (const float*)d_in[2];
    const float* Wx   = (const float*)d_in[3];
    const float* bx   = (const float*)d_in[4];
    const float* Wqp  = (const float*)d_in[5];
    const float* Wkp  = (const float*)d_in[6];
    const float* Wvp  = (const float*)d_in[7];
    const float* Wo   = (const float*)d_in[8];
    const float* bo   = (const float*)d_in[9];
    const float* ln2w = (const float*)d_in[10];
    const float* ln2b = (const float*)d_in[11];
    const float* W1   = (const float*)d_in[12];
    const float* b1   = (const float*)d_in[13];
    const float* W2   = (const float*)d_in[14];
    const float* b2   = (const float*)d_in[15];
    float* out = (float*)d_out;

    __half *p_xln, *p_q, *p_qkv, *p_y, *p_hid, *p_Wx, *p_Wo, *p_W1, *p_W2;
    float  *p_xmid, *p_h;
    cudaGetSymbolAddress((void**)&p_xln,  g_xln_h);
    cudaGetSymbolAddress((void**)&p_xmid, g_xmid);
    cudaGetSymbolAddress((void**)&p_q,    g_q_h);
    cudaGetSymbolAddress((void**)&p_qkv,  g_qkv_h);
    cudaGetSymbolAddress((void**)&p_h,    g_h);
    cudaGetSymbolAddress((void**)&p_y,    g_y_h);
    cudaGetSymbolAddress((void**)&p_hid,  g_hid_h);
    cudaGetSymbolAddress((void**)&p_Wx,   g_Wx_h);
    cudaGetSymbolAddress((void**)&p_Wo,   g_Wo_h);
    cudaGetSymbolAddress((void**)&p_W1,   g_W1_h);
    cudaGetSymbolAddress((void**)&p_W2,   g_W2_h);

    cudaFuncSetAttribute(hgemm_kernel<0,0>, cudaFuncAttributeMaxDynamicSharedMemorySize, GEMM_SMEM);
    cudaFuncSetAttribute(hgemm_kernel<1,0>, cudaFuncAttributeMaxDynamicSharedMemorySize, GEMM_SMEM);
    cudaFuncSetAttribute(hgemm_kernel<2,1>, cudaFuncAttributeMaxDynamicSharedMemorySize, GEMM_SMEM);

    // 0) weight conversion fp32 -> fp16
    f2h_kernel<<<(Cq * Cq / 4 + 255) / 256, 256>>>(Wx, p_Wx, Cq * Cq / 4);
    f2h_kernel<<<(Cq * Cq / 4 + 255) / 256, 256>>>(Wo, p_Wo, Cq * Cq / 4);
    f2h_kernel<<<(HIDq * Cq / 4 + 255) / 256, 256>>>(W1, p_W1, HIDq * Cq / 4);
    f2h_kernel<<<(Cq * HIDq / 4 + 255) / 256, 256>>>(W2, p_W2, Cq * HIDq / 4);

    dim3 lnBlk(32, 8);
    // 1) LN1 -> fp16
    ln_kernel<<<Mq / 8, lnBlk>>>(fx, ln1w, ln1b, p_xln);
    // 2) x_mid = xln @ Wx^T + bx  (fp16 mma, fp32 out)
    hgemm_kernel<0,0><<<dim3(Cq / BN, Mq / BM), 256, GEMM_SMEM>>>(
        p_xln, p_Wx, bx, nullptr, p_xmid, nullptr, Cq, Cq);
    // 3) fused per-head q/softmax + partial kv reduction (no ek/v in HBM)
    head_proj_fused_kernel<<<dim3(KV_CHUNKS, Hq, Bq), 128>>>(
        p_xmid, Wqp, Wkp, Wvp, p_q);
    // 4) finalize kv
    kv_finalize_kernel<<<BHq, 256>>>();
    // 5) qkv = q @ kv  (fp16 in/out)
    qkv_apply_kernel<<<dim3(Nq / 128, Hq, Bq), 128>>>(p_q, p_qkv);
    // 6) h = qkv @ Wo^T + bo + fx  (fp32 out)
    hgemm_kernel<1,0><<<dim3(Cq / BN, Mq / BM), 256, GEMM_SMEM>>>(
        p_qkv, p_Wo, bo, fx, p_h, nullptr, Cq, Cq);
    // 7) LN2 -> fp16
    ln_kernel<<<Mq / 8, lnBlk>>>(p_h, ln2w, ln2b, p_y);
    // 8) hid = gelu(y @ W1^T + b1)  (fp16 out)
    hgemm_kernel<2,1><<<dim3(HIDq / BN, Mq / BM), 256, GEMM_SMEM>>>(
        p_y, p_W1, b1, nullptr, nullptr, p_hid, HIDq, Cq);
    // 9) out = hid @ W2^T + b2 + h  (fp32 out)
    hgemm_kernel<1,0><<<dim3(Cq / BN, Mq / BM), 256, GEMM_SMEM>>>(
        p_hid, p_W2, b2, p_h, out, nullptr, Cq, HIDq);
}

// round 7
// speedup vs baseline: 4.6802x; 1.0292x over previous
#include <cuda_runtime.h>
#include <cuda_fp16.h>
#include <math.h>
#include <stdint.h>

// Problem constants
#define Bq   8
#define Nq   8192
#define Cq   256
#define Hq   8
#define Dq   32
#define Sq   32
#define HIDq 1024
#define Mq   (Bq * Nq)        // 65536 rows
#define BHq  (Bq * Hq)        // 64
#define KV_CHUNKS 64          // one chunk per 128-token head_proj CTA

// GEMM tiling (fp16 mma m16n8k16)
#define BM 128
#define BN 128
#define BKH 64                          // K-halves per tile (128 bytes/row)
#define STAGE_BYTES (2 * BM * BKH * 2)  // A tile + B tile = 32KB
#define GEMM_SMEM (2 * STAGE_BYTES)     // 2 stages = 64KB

// ---------------- scratch (static device arrays; no allocation) -------------
__device__ __half g_xln_h[Mq * Cq];
__device__ float  g_xmid [Mq * Cq];
__device__ __half g_q_h  [(size_t)Mq * Cq];             // [b][n][h*32+s]
__device__ float  g_ekvp [KV_CHUNKS * BHq * Sq * Dq];   // per-chunk partial kv
__device__ float  g_csp  [KV_CHUNKS * BHq * Sq];        // per-chunk col sums
__device__ __half g_KW   [Bq * Cq * Cq];                // KW[b][c][h*32+s]
__device__ float  g_h    [Mq * Cq];
__device__ __half g_y_h  [Mq * Cq];
__device__ __half g_hid_h[Mq * HIDq];
__device__ __half g_Wx_h [Cq * Cq];
__device__ __half g_W1_h [HIDq * Cq];
__device__ __half g_W2_h [Cq * HIDq];

// ------------------------------ PTX helpers ---------------------------------
__device__ __forceinline__ uint32_t smem_u32(const void* p) {
    uint32_t a;
    asm("{ .reg .u64 t; cvta.to.shared.u64 t, %1; cvt.u32.u64 %0, t; }"
        : "=r"(a) : "l"(p));
    return a;
}
__device__ __forceinline__ void cp_async16(uint32_t dst, const void* src) {
    asm volatile("cp.async.ca.shared.global [%0], [%1], 16;"
                 :: "r"(dst), "l"(src));
}
__device__ __forceinline__ void cp_commit() {
    asm volatile("cp.async.commit_group;");
}
template <int N>
__device__ __forceinline__ void cp_wait() {
    asm volatile("cp.async.wait_group %0;" :: "n"(N));
}
__device__ __forceinline__ void ldsm4(uint32_t* r, uint32_t addr) {
    asm volatile("ldmatrix.sync.aligned.m8n8.x4.shared.b16 {%0,%1,%2,%3}, [%4];"
                 : "=r"(r[0]), "=r"(r[1]), "=r"(r[2]), "=r"(r[3]) : "r"(addr));
}
__device__ __forceinline__ void mma_f16(float* c, const uint32_t* a, const uint32_t* b) {
    asm volatile(
        "mma.sync.aligned.m16n8k16.row.col.f32.f16.f16.f32 "
        "{%0,%1,%2,%3}, {%4,%5,%6,%7}, {%8,%9}, {%0,%1,%2,%3};"
        : "+f"(c[0]), "+f"(c[1]), "+f"(c[2]), "+f"(c[3])
        : "r"(a[0]), "r"(a[1]), "r"(a[2]), "r"(a[3]), "r"(b[0]), "r"(b[1]));
}

// ---------------- fp32 -> fp16 weight conversion (one launch) ----------------
#define F4_WX (Cq * Cq / 4)            // 16384
#define F4_W1 (HIDq * Cq / 4)          // 65536
#define F4_W2 (Cq * HIDq / 4)          // 65536
#define F4_TOTAL (F4_WX + F4_W1 + F4_W2)

__global__ void f2h_all_kernel(const float* __restrict__ Wx,
                               const float* __restrict__ W1,
                               const float* __restrict__ W2,
                               __half* oWx, __half* oW1, __half* oW2) {
    int i = blockIdx.x * 256 + threadIdx.x;
    if (i >= F4_TOTAL) return;
    const float* src; __half* dst; int j;
    if (i < F4_WX)                { src = Wx; dst = oWx; j = i; }
    else if (i < F4_WX + F4_W1)   { src = W1; dst = oW1; j = i - F4_WX; }
    else                          { src = W2; dst = oW2; j = i - F4_WX - F4_W1; }
    float4 v = ((const float4*)src)[j];
    ((__half2*)dst)[j * 2]     = __floats2half2_rn(v.x, v.y);
    ((__half2*)dst)[j * 2 + 1] = __floats2half2_rn(v.z, v.w);
}

// ---------------- LayerNorm: one warp per row (C=256), fp16 out -------------
__global__ void ln_kernel(const float* __restrict__ x,
                          const float* __restrict__ w,
                          const float* __restrict__ bb,
                          __half* __restrict__ out) {
    int row  = blockIdx.x * 8 + threadIdx.y;
    int lane = threadIdx.x;
    const float* xr = x + (size_t)row * Cq;
    float v[8];
    float s = 0.f, s2 = 0.f;
#pragma unroll
    for (int i = 0; i < 8; i++) {
        float t = xr[lane + i * 32];
        v[i] = t; s += t; s2 += t * t;
    }
#pragma unroll
    for (int o = 16; o > 0; o >>= 1) {
        s  += __shfl_xor_sync(0xffffffffu, s,  o);
        s2 += __shfl_xor_sync(0xffffffffu, s2, o);
    }
    float mu  = s * (1.f / Cq);
    float var = s2 * (1.f / Cq) - mu * mu;
    float rs  = rsqrtf(var + 1e-5f);
    __half* orow = out + (size_t)row * Cq;
#pragma unroll
    for (int i = 0; i < 8; i++) {
        int c = lane + i * 32;
        orow[c] = __float2half_rn((v[i] - mu) * rs * w[c] + bb[c]);
    }
}

// ------------- fp16 mma GEMM: C = A[M,K] @ W[Ncols,K]^T + bias --------------
// Optionally batched over blockIdx.z with element strides sA/sW/sC.
__device__ __forceinline__ float gelu_exact(float v) {
    return 0.5f * v * (1.f + erff(v * 0.70710678118654752f));
}

template <int EPI, int OUT16>
__global__ __launch_bounds__(256) void hgemm_kernel(
    const __half* __restrict__ A, const __half* __restrict__ W,
    const float* __restrict__ bias, const float* __restrict__ res,
    float* __restrict__ Cout, __half* __restrict__ Cout16,
    int Ncols, int K, size_t sA, size_t sW, size_t sC) {
    extern __shared__ char smem[];
    int tid  = threadIdx.x;
    int wid  = tid >> 5, lane = tid & 31;
    int g = lane >> 2, q = lane & 3;
    int warp_m = wid >> 2;
    int warp_n = wid & 3;
    size_t zoffC = sC * blockIdx.z;

    uint32_t sbase = smem_u32(smem);
    const __half* Ab = A + sA * blockIdx.z + (size_t)blockIdx.y * BM * K;
    const __half* Wb = W + sW * blockIdx.z + (size_t)blockIdx.x * BN * K;

    float acc[4][4][4];
#pragma unroll
    for (int mt = 0; mt < 4; mt++)
#pragma unroll
        for (int nt = 0; nt < 4; nt++)
#pragma unroll
            for (int i = 0; i < 4; i++) acc[mt][nt][i] = 0.f;

    int ntiles = K / BKH;

    auto load_tile = [&](int stage, int kt) {
        uint32_t aoff = sbase + stage * STAGE_BYTES;
        uint32_t boff = aoff + BM * BKH * 2;
        int k0 = kt * BKH;
#pragma unroll
        for (int i = 0; i < 4; i++) {
            int idx  = i * 256 + tid;
            int row  = idx >> 3;
            int grp  = idx & 7;
            int phys = grp ^ (row & 7);
            cp_async16(aoff + (row * 8 + phys) * 16, &Ab[(size_t)row * K + k0 + grp * 8]);
            cp_async16(boff + (row * 8 + phys) * 16, &Wb[(size_t)row * K + k0 + grp * 8]);
        }
    };

    load_tile(0, 0);
    cp_commit();

    for (int kt = 0; kt < ntiles; kt++) {
        int cur = kt & 1;
        if (kt + 1 < ntiles) {
            load_tile(cur ^ 1, kt + 1);
            cp_commit();
            cp_wait<1>();
        } else {
            cp_wait<0>();
        }
        __syncthreads();

        uint32_t sAb = sbase + cur * STAGE_BYTES;
        uint32_t sBb = sAb + BM * BKH * 2;

#pragma unroll
        for (int ks = 0; ks < 4; ks++) {
            uint32_t af[4][4];
#pragma unroll
            for (int mt = 0; mt < 4; mt++) {
                int row = warp_m * 64 + mt * 16 + (lane & 15);
                int kg  = 2 * ks + (lane >> 4);
                ldsm4(af[mt], sAb + (row * 8 + (kg ^ (row & 7))) * 16);
            }
            uint32_t bf[2][4];
#pragma unroll
            for (int p = 0; p < 2; p++) {
                int n  = warp_n * 32 + p * 16 + (lane >> 4) * 8 + (lane & 7);
                int kg = 2 * ks + ((lane >> 3) & 1);
                ldsm4(bf[p], sBb + (n * 8 + (kg ^ (n & 7))) * 16);
            }
#pragma unroll
            for (int mt = 0; mt < 4; mt++)
#pragma unroll
                for (int nt = 0; nt < 4; nt++)
                    mma_f16(acc[mt][nt], af[mt], &bf[nt >> 1][(nt & 1) * 2]);
        }
        __syncthreads();
    }

    int mBase = blockIdx.y * BM + warp_m * 64;
    int nBase = blockIdx.x * BN + warp_n * 32;
#pragma unroll
    for (int nt = 0; nt < 4; nt++) {
        int c0 = nBase + nt * 8 + q * 2;
        float bv0 = bias[c0], bv1 = bias[c0 + 1];
#pragma unroll
        for (int mt = 0; mt < 4; mt++) {
            int r0 = mBase + mt * 16 + g;
#pragma unroll
            for (int half = 0; half < 2; half++) {
                int r = r0 + half * 8;
                size_t off = (size_t)r * Ncols + c0 + zoffC;
                float v0 = acc[mt][nt][half * 2 + 0] + bv0;
                float v1 = acc[mt][nt][half * 2 + 1] + bv1;
                if (EPI == 1) {
                    float2 rr = *(const float2*)&res[off];
                    v0 += rr.x; v1 += rr.y;
                }
                if (EPI == 2) { v0 = gelu_exact(v0); v1 = gelu_exact(v1); }
                if (OUT16) {
                    *(__half2*)&Cout16[off] = __floats2half2_rn(v0, v1);
                } else {
                    *(float2*)&Cout[off] = make_float2(v0, v1);
                }
            }
        }
    }
}

// ------- fused per-head projection + softmaxes + partial kv reduction -------
// block = 128 tokens of one (b,h); thread = one token.
// q written fp16 in [b][n][h*32+s] layout; partial kv via warp-shuffle.
__global__ __launch_bounds__(128) void head_proj_fused_kernel(
    const float* __restrict__ xmid,
    const float* __restrict__ Wq, const float* __restrict__ Wk,
    const float* __restrict__ Wv,
    __half* __restrict__ qo) {
    __shared__ float xs[128][33];   // x tile; then ek tile
    __shared__ float vs[128][33];   // v tile
    __shared__ float csbuf[4][32];
    __shared__ float wq[Sq * Dq], wk[Sq * Dq], wv[Dq * Dq];
    int tid = threadIdx.x;
    int wrp = tid >> 5, lane = tid & 31;
    int h = blockIdx.y, b = blockIdx.z;
    int ch = blockIdx.x;
    int n0 = ch * 128;
    int bh = b * Hq + h;

#pragma unroll
    for (int i = 0; i < 8; i++) {
        int idx = tid + i * 128;
        wq[idx] = Wq[idx]; wk[idx] = Wk[idx]; wv[idx] = Wv[idx];
    }
    size_t base = ((size_t)(b * Nq + n0)) * Cq + h * Dq;
#pragma unroll
    for (int i = 0; i < 32; i++) {
        int idx = tid + i * 128;
        int t = idx >> 5, d = idx & 31;
        xs[t][d] = xmid[base + (size_t)t * Cq + d];
    }
    __syncthreads();

    float x[32];
#pragma unroll
    for (int d = 0; d < 32; d++) x[d] = xs[tid][d];
    __syncthreads();

    // --- q = softmax_s(x @ Wq^T), fp16, layout [b][n][h*32+s] ---
    {
        float e[32]; float ssum = 0.f;
#pragma unroll
        for (int s = 0; s < 32; s++) {
            float a = 0.f;
#pragma unroll
            for (int d = 0; d < 32; d++) a += x[d] * wq[s * 32 + d];
            e[s] = expf(a); ssum += e[s];
        }
        float r = 1.f / ssum;
        __half2 qh[16];
#pragma unroll
        for (int s = 0; s < 16; s++)
            qh[s] = __floats2half2_rn(e[2 * s] * r, e[2 * s + 1] * r);
        size_t qoff = ((size_t)(b * Nq + n0 + tid)) * Cq + h * 32;
        uint4* dst = (uint4*)(qo + qoff);
#pragma unroll
        for (int i = 0; i < 4; i++) dst[i] = ((uint4*)qh)[i];
    }

    // --- ek = exp(x @ Wk^T) -> xs;  v = x @ Wv^T -> vs ---
#pragma unroll
    for (int s = 0; s < 32; s++) {
        float a = 0.f;
#pragma unroll
        for (int d = 0; d < 32; d++) a += x[d] * wk[s * 32 + d];
        xs[tid][s] = expf(a);
    }
#pragma unroll
    for (int dp = 0; dp < 32; dp++) {
        float a = 0.f;
#pragma unroll
        for (int d = 0; d < 32; d++) a += x[d] * wv[dp * 32 + d];
        vs[tid][dp] = a;
    }
    __syncthreads();

    // --- partial kv via shfl: warp w covers tokens [w*32, w*32+32) ---
    // lane owns s = lane; accumulates a[d] = sum_t ek[t][s] * v[t][d]
    float a[32];
#pragma unroll
    for (int d = 0; d < 32; d++) a[d] = 0.f;
    float cs = 0.f;
#pragma unroll 2
    for (int tt = 0; tt < 32; tt++) {
        int t = wrp * 32 + tt;
        float e  = xs[t][lane];
        float vv = vs[t][lane];
        cs += e;
#pragma unroll
        for (int d = 0; d < 32; d++)
            a[d] += e * __shfl_sync(0xffffffffu, vv, d);
    }
    csbuf[wrp][lane] = cs;
    __syncthreads();   // xs free now (all reads done)

    // stash warp partials: xs[w*32 + s][d] = a[d]
#pragma unroll
    for (int d = 0; d < 32; d++) xs[wrp * 32 + lane][d] = a[d];
    __syncthreads();

    // final: thread covers (s = tid&31, 8 d's)
    int s  = tid & 31;
    int d0 = (tid >> 5) * 8;
    float r[8];
#pragma unroll
    for (int j = 0; j < 8; j++) {
        r[j] = xs[s][d0 + j] + xs[32 + s][d0 + j]
             + xs[64 + s][d0 + j] + xs[96 + s][d0 + j];
    }
    float* ep = &g_ekvp[((size_t)ch * BHq + bh) * (Sq * Dq) + s * 32 + d0];
#pragma unroll
    for (int j = 0; j < 8; j++) ep[j] = r[j];
    if (tid < 32)
        g_csp[((size_t)ch * BHq + bh) * Sq + s] =
            csbuf[0][s] + csbuf[1][s] + csbuf[2][s] + csbuf[3][s];
}

// ---- kv finalize + KW = kv @ Wo_h^T  (fp16 [b][c][h*32+s]) ------------------
__global__ __launch_bounds__(256) void kvw_kernel(const float* __restrict__ Wo,
                                                  __half* __restrict__ KW) {
    int bh = blockIdx.x;
    int b = bh >> 3, h = bh & 7;
    int tid = threadIdx.x;
    __shared__ float kvs[32][33];
    __shared__ float rcs[32];

    if (tid < 32) {
        float c = 0.f;
#pragma unroll
        for (int ch = 0; ch < KV_CHUNKS; ch++)
            c += g_csp[((size_t)ch * BHq + bh) * Sq + tid];
        rcs[tid] = 1.f / c;
    }
    __syncthreads();
#pragma unroll
    for (int rep = 0; rep < 4; rep++) {
        int idx = tid + rep * 256;
        int s = idx >> 5, d = idx & 31;
        float vsum = 0.f;
#pragma unroll
        for (int ch = 0; ch < KV_CHUNKS; ch++)
            vsum += g_ekvp[((size_t)ch * BHq + bh) * (Sq * Dq) + idx];
        kvs[s][d] = vsum * rcs[s];
    }
    __syncthreads();

    // thread = output channel c; KW[b][c][h*32+s] = sum_d kv[s][d]*Wo[c][h*32+d]
    int c = tid;
    float wo[32];
#pragma unroll
    for (int d = 0; d < 32; d++) wo[d] = Wo[(size_t)c * Cq + h * 32 + d];
    __half2 outv[16];
#pragma unroll
    for (int sp = 0; sp < 16; sp++) {
        float a0 = 0.f, a1 = 0.f;
#pragma unroll
        for (int d = 0; d < 32; d++) {
            a0 += kvs[2 * sp][d] * wo[d];
            a1 += kvs[2 * sp + 1][d] * wo[d];
        }
        outv[sp] = __floats2half2_rn(a0, a1);
    }
    uint4* dst = (uint4*)&KW[((size_t)b * Cq + c) * Cq + h * 32];
#pragma unroll
    for (int i = 0; i < 4; i++) dst[i] = ((uint4*)outv)[i];
}

// ---------------------------- launcher ---------------------------------------
extern "C" void kernel_launch(void* const* d_in, const int* in_sizes, int n_in,
                              void* d_out, int out_size) {
    const float* fx   = (const float*)d_in[0];
    const float* ln1w = (const float*)d_in[1];
    const float* ln1b = (const float*)d_in[2];
    const float* Wx   = (const float*)d_in[3];
    const float* bx   = (const float*)d_in[4];
    const float* Wqp  = (const float*)d_in[5];
    const float* Wkp  = (const float*)d_in[6];
    const float* Wvp  = (const float*)d_in[7];
    const float* Wo   = (const float*)d_in[8];
    const float* bo   = (const float*)d_in[9];
    const float* ln2w = (const float*)d_in[10];
    const float* ln2b = (const float*)d_in[11];
    const float* W1   = (const float*)d_in[12];
    const float* b1   = (const float*)d_in[13];
    const float* W2   = (const float*)d_in[14];
    const float* b2   = (const float*)d_in[15];
    float* out = (float*)d_out;

    __half *p_xln, *p_q, *p_KW, *p_y, *p_hid, *p_Wx, *p_W1, *p_W2;
    float  *p_xmid, *p_h;
    cudaGetSymbolAddress((void**)&p_xln,  g_xln_h);
    cudaGetSymbolAddress((void**)&p_xmid, g_xmid);
    cudaGetSymbolAddress((void**)&p_q,    g_q_h);
    cudaGetSymbolAddress((void**)&p_KW,   g_KW);
    cudaGetSymbolAddress((void**)&p_h,    g_h);
    cudaGetSymbolAddress((void**)&p_y,    g_y_h);
    cudaGetSymbolAddress((void**)&p_hid,  g_hid_h);
    cudaGetSymbolAddress((void**)&p_Wx,   g_Wx_h);
    cudaGetSymbolAddress((void**)&p_W1,   g_W1_h);
    cudaGetSymbolAddress((void**)&p_W2,   g_W2_h);

    cudaFuncSetAttribute(hgemm_kernel<0,0>, cudaFuncAttributeMaxDynamicSharedMemorySize, GEMM_SMEM);
    cudaFuncSetAttribute(hgemm_kernel<1,0>, cudaFuncAttributeMaxDynamicSharedMemorySize, GEMM_SMEM);
    cudaFuncSetAttribute(hgemm_kernel<2,1>, cudaFuncAttributeMaxDynamicSharedMemorySize, GEMM_SMEM);

    // 0) weight conversion (single launch)
    f2h_all_kernel<<<(F4_TOTAL + 255) / 256, 256>>>(Wx, W1, W2, p_Wx, p_W1, p_W2);

    dim3 lnBlk(32, 8);
    // 1) LN1 -> fp16
    ln_kernel<<<Mq / 8, lnBlk>>>(fx, ln1w, ln1b, p_xln);
    // 2) x_mid = xln @ Wx^T + bx
    hgemm_kernel<0,0><<<dim3(Cq / BN, Mq / BM, 1), 256, GEMM_SMEM>>>(
        p_xln, p_Wx, bx, nullptr, p_xmid, nullptr, Cq, Cq, 0, 0, 0);
    // 3) fused per-head q/softmax + partial kv reduction
    head_proj_fused_kernel<<<dim3(KV_CHUNKS, Hq, Bq), 128>>>(
        p_xmid, Wqp, Wkp, Wvp, p_q);
    // 4) finalize kv + KW = kv @ Wo^T (per batch, fp16)
    kvw_kernel<<<BHq, 256>>>(Wo, p_KW);
    // 5) h = q @ KW^T + bo + fx  (batched over b; replaces qkv_apply + Wo GEMM)
    hgemm_kernel<1,0><<<dim3(Cq / BN, Nq / BM, Bq), 256, GEMM_SMEM>>>(
        p_q, p_KW, bo, fx, p_h, nullptr, Cq, Cq,
        (size_t)Nq * Cq, (size_t)Cq * Cq, (size_t)Nq * Cq);
    // 6) LN2 -> fp16
    ln_kernel<<<Mq / 8, lnBlk>>>(p_h, ln2w, ln2b, p_y);
    // 7) hid = gelu(y @ W1^T + b1)  (fp16 out)
    hgemm_kernel<2,1><<<dim3(HIDq / BN, Mq / BM, 1), 256, GEMM_SMEM>>>(
        p_y, p_W1, b1, nullptr, nullptr, p_hid, HIDq, Cq, 0, 0, 0);
    // 8) out = hid @ W2^T + b2 + h
    hgemm_kernel<1,0><<<dim3(Cq / BN, Mq / BM, 1), 256, GEMM_SMEM>>>(
        p_hid, p_W2, b2, p_h, out, nullptr, Cq, HIDq, 0, 0, 0);
}